// round 14
// baseline (speedup 1.0000x reference)
#include <cuda_runtime.h>
#include <cuda_fp16.h>
#include <math.h>
#include <stdint.h>

#define H 256
#define N_MAX 10240
#define E_MAX 163840
#define L_MAX 3

#define BM 128
#define BN 256
#define BK 32
#define NTH 256
#define NSTAGE 5

// ---------------- scratch (device globals) ---------------------------------
__device__ __half g_ghh[E_MAX * H];            // gh fp16, PERMUTED by dst-sorted order
__device__ __half g_nfh[N_MAX * 128];
__device__ __half g_nfl[N_MAX * 128];
__device__ __half g_hh[2][N_MAX * H];
__device__ __half g_hl[2][N_MAX * H];
__device__ __half g_Wh[L_MAX * 1024 * 256];
__device__ __half g_wnh[128 * 256];
__device__ __half g_P[2 * N_MAX * H];
__device__ float g_eps[N_MAX];
__device__ float g_ae[E_MAX];
__device__ int g_cnt[N_MAX];
__device__ int g_off[N_MAX + 1];
__device__ int g_cur[N_MAX];
__device__ int g_perm[E_MAX];
__device__ int g_srcp[E_MAX];
__device__ int g_dstp[E_MAX];

// ---------------- helpers ----------------------------------------------------
__device__ __forceinline__ uint32_t smem_u32(const void* p) {
    uint32_t a;
    asm("{ .reg .u64 t; cvta.to.shared.u64 t, %1; cvt.u32.u64 %0, t; }" : "=r"(a) : "l"(p));
    return a;
}
__device__ __forceinline__ void cp16(uint32_t dst, const void* src) {
    asm volatile("cp.async.cg.shared.global [%0], [%1], 16;" :: "r"(dst), "l"(src));
}
__device__ __forceinline__ void ldsm4(uint32_t* r, uint32_t addr) {
    asm volatile("ldmatrix.sync.aligned.m8n8.x4.shared.b16 {%0,%1,%2,%3}, [%4];"
                 : "=r"(r[0]), "=r"(r[1]), "=r"(r[2]), "=r"(r[3]) : "r"(addr));
}
__device__ __forceinline__ void ldsm4t(uint32_t* r, uint32_t addr) {
    asm volatile("ldmatrix.sync.aligned.m8n8.x4.trans.shared.b16 {%0,%1,%2,%3}, [%4];"
                 : "=r"(r[0]), "=r"(r[1]), "=r"(r[2]), "=r"(r[3]) : "r"(addr));
}
__device__ __forceinline__ void mma16816(float* c, const uint32_t* a, const uint32_t* b) {
    asm volatile("mma.sync.aligned.m16n8k16.row.col.f32.f16.f16.f32 "
                 "{%0,%1,%2,%3}, {%4,%5,%6,%7}, {%8,%9}, {%0,%1,%2,%3};"
                 : "+f"(c[0]), "+f"(c[1]), "+f"(c[2]), "+f"(c[3])
                 : "r"(a[0]), "r"(a[1]), "r"(a[2]), "r"(a[3]), "r"(b[0]), "r"(b[1]));
}

// ---------------- weight prep (hi only) + csr clear ---------------------------
__global__ void prep_w(const float* __restrict__ a_w1, const float* __restrict__ eps_w1,
                       const float* __restrict__ Wn_w, int L, int N)
{
    const int totW = L * 1024 * 256;
    const int total = totW + 128 * 256;
    int idx = blockIdx.x * blockDim.x + threadIdx.x;
    if (idx < N) g_cnt[idx] = 0;
    if (idx >= total) return;
    float v;
    __half* dh;
    int di;
    if (idx < totW) {
        int l = idx / (1024 * 256);
        int r = (idx / 256) % 1024;
        int n = idx % 256;
        if (r < 512)      v = a_w1[((size_t)l * 768 + r) * 256 + n];
        else if (r < 768) v = eps_w1[((size_t)l * 256 + (r - 512)) * 256 + n];
        else              v = a_w1[((size_t)l * 768 + 512 + (r - 768)) * 256 + n];
        dh = g_Wh; di = idx;
    } else {
        int i2 = idx - totW;
        v = Wn_w[i2];
        dh = g_wnh; di = i2;
    }
    dh[di] = __float2half(v);
}

// ---------------- nf cvt (fp16 hi/lo) + csr_hist fused ------------------------
__global__ void cvt_nf_hist(const float* __restrict__ x, __half* __restrict__ hi,
                            __half* __restrict__ lo, int n4,
                            const int* __restrict__ dst, int E)
{
    int i = blockIdx.x * blockDim.x + threadIdx.x;
    if (i < E) atomicAdd(&g_cnt[dst[i]], 1);
    if (i >= n4) return;
    float4 v = ((const float4*)x)[i];
    __half h0 = __float2half(v.x), h1 = __float2half(v.y);
    __half h2 = __float2half(v.z), h3 = __float2half(v.w);
    ((__half2*)hi)[i * 2 + 0] = __half2(h0, h1);
    ((__half2*)hi)[i * 2 + 1] = __half2(h2, h3);
    ((__half2*)lo)[i * 2 + 0] = __half2(__float2half(v.x - __half2float(h0)),
                                        __float2half(v.y - __half2float(h1)));
    ((__half2*)lo)[i * 2 + 1] = __half2(__float2half(v.z - __half2float(h2)),
                                        __float2half(v.w - __half2float(h3)));
}

// ---------------- CSR scan (warp-shuffle two-level) ----------------------------
__global__ void csr_scan(int N, int E) {
    __shared__ int wsum[32];
    const int tid = threadIdx.x;
    const int lane = tid & 31;
    const int wrp = tid >> 5;
    const int chunk = (N + 1023) / 1024;
    const int base = tid * chunk;
    int s = 0;
#pragma unroll 4
    for (int i = 0; i < chunk; i++) {
        int idx = base + i;
        if (idx < N) s += g_cnt[idx];
    }
    int sc = s;
#pragma unroll
    for (int o = 1; o < 32; o <<= 1) {
        int v = __shfl_up_sync(0xffffffffu, sc, o);
        if (lane >= o) sc += v;
    }
    if (lane == 31) wsum[wrp] = sc;
    __syncthreads();
    if (wrp == 0) {
        int t = wsum[lane];
#pragma unroll
        for (int o = 1; o < 32; o <<= 1) {
            int v = __shfl_up_sync(0xffffffffu, t, o);
            if (lane >= o) t += v;
        }
        wsum[lane] = t;
    }
    __syncthreads();
    int run = sc - s + (wrp ? wsum[wrp - 1] : 0);
    for (int i = 0; i < chunk; i++) {
        int idx = base + i;
        if (idx < N) { g_off[idx] = run; g_cur[idx] = run; run += g_cnt[idx]; }
    }
    if (tid == 1023) g_off[N] = E;
}

__global__ void csr_scatter(const int* __restrict__ src, const int* __restrict__ dst,
                            int E)
{
    int e = blockIdx.x * blockDim.x + threadIdx.x;
    if (e < E) {
        int d = dst[e];
        int pos = atomicAdd(&g_cur[d], 1);
        g_perm[pos] = e;
        g_srcp[pos] = src[e];
        g_dstp[pos] = d;
    }
}

__global__ void cvt_gh_perm(const float* __restrict__ gh, __half* __restrict__ hi,
                            int n4)
{
    int i = blockIdx.x * blockDim.x + threadIdx.x;
    if (i >= n4) return;
    const int row = i >> 6;
    const int c4 = i & 63;
    const int e = g_perm[row];
    float4 v = ((const float4*)(gh + (size_t)e * H))[c4];
    __half2 hh0(__float2half(v.x), __float2half(v.y));
    __half2 hh1(__float2half(v.z), __float2half(v.w));
    ((__half2*)hi)[i * 2 + 0] = hh0;
    ((__half2*)hi)[i * 2 + 1] = hh1;
}

// ============ GEMM body macros (R12 tiling: wm=wid&3, wn=wid>>2) ==============
#define GEMM_MAINLOOP(HAS_AL)                                                  \
    constexpr uint32_t AH_OFF = 0;                                             \
    constexpr uint32_t AL_OFF = 8192;                                          \
    constexpr uint32_t BH_OFF = (HAS_AL) ? 16384u : 8192u;                     \
    constexpr uint32_t STB = BH_OFF + 16384u;                                  \
    float acc[2][16][4];                                                       \
    _Pragma("unroll") for (int mi = 0; mi < 2; mi++)                           \
    _Pragma("unroll") for (int nj = 0; nj < 16; nj++)                          \
    _Pragma("unroll") for (int q = 0; q < 4; q++) acc[mi][nj][q] = 0.f;        \
    const int nchunks = K / BK;                                                \
    auto load_stage = [&](int s, int k0) {                                     \
        const uint32_t base = sb + s * STB;                                    \
        _Pragma("unroll") for (int i = 0; i < 2; i++) {                        \
            int cid = tid + i * NTH;                                           \
            int row = cid >> 2;                                                \
            int cb = (cid & 3) * 16;                                           \
            int grow = m0 + row;                                               \
            if (grow >= M) grow = M - 1;                                       \
            size_t gb = ((size_t)grow * K + k0) * 2 + cb;                      \
            uint32_t d = base + row * 64 + (cb ^ ((row & 3) << 4));            \
            cp16(d + AH_OFF, (const char*)A + gb);                             \
            if (HAS_AL) cp16(d + AL_OFF, (const char*)AL + gb);                \
        }                                                                      \
        _Pragma("unroll") for (int i = 0; i < 4; i++) {                        \
            int cid = tid + i * NTH;                                           \
            int k = cid >> 5;                                                  \
            int cb = (cid & 31) * 16;                                          \
            size_t gb = (size_t)(k0 + k) * 512 + cb;                           \
            uint32_t d = base + k * 512 + (cb ^ ((k & 7) << 4));               \
            cp16(d + BH_OFF, (const char*)Bz + gb);                            \
        }                                                                      \
        asm volatile("cp.async.commit_group;" ::: "memory");                   \
    };                                                                         \
    auto compute_stage = [&](int s) {                                          \
        const uint32_t base = sb + s * STB;                                    \
        _Pragma("unroll") for (int kk = 0; kk < 2; kk++) {                     \
            uint32_t ah[2][4], al[2][4];                                       \
            _Pragma("unroll") for (int mi = 0; mi < 2; mi++) {                 \
                int row = wm * 32 + mi * 16 + (lane & 15);                     \
                uint32_t cb = kk * 32 + ((lane >> 4) << 4);                    \
                uint32_t ad = base + row * 64 + (cb ^ ((row & 3) << 4));       \
                ldsm4(ah[mi], ad + AH_OFF);                                    \
                if (HAS_AL) ldsm4(al[mi], ad + AL_OFF);                        \
            }                                                                  \
            const int kr = kk * 16 + (lane & 15);                              \
            const uint32_t hi16 = (lane >> 4) << 4;                            \
            uint32_t bhA[4], bhB[4];                                           \
            {                                                                  \
                uint32_t cb = wn * 256 + hi16;                                 \
                uint32_t bd = base + kr * 512 + (cb ^ ((kr & 7) << 4));        \
                ldsm4t(bhA, bd + BH_OFF);                                      \
            }                                                                  \
            _Pragma("unroll") for (int nj2 = 0; nj2 < 8; nj2++) {              \
                uint32_t* ch = (nj2 & 1) ? bhB : bhA;                          \
                if (nj2 < 7) {                                                 \
                    uint32_t* nh = (nj2 & 1) ? bhA : bhB;                      \
                    uint32_t cb = wn * 256 + (nj2 + 1) * 32 + hi16;            \
                    uint32_t bd = base + kr * 512 + (cb ^ ((kr & 7) << 4));    \
                    ldsm4t(nh, bd + BH_OFF);                                   \
                }                                                              \
                _Pragma("unroll") for (int mi = 0; mi < 2; mi++)               \
                _Pragma("unroll") for (int sub = 0; sub < 2; sub++) {          \
                    int nj = nj2 * 2 + sub;                                    \
                    mma16816(acc[mi][nj], ah[mi], &ch[sub * 2]);               \
                    if (HAS_AL) mma16816(acc[mi][nj], al[mi], &ch[sub * 2]);   \
                }                                                              \
            }                                                                  \
        }                                                                      \
    };                                                                         \
    for (int p = 0; p < 3 && p < nchunks; p++) load_stage(p, p * BK);          \
    {                                                                          \
        int cs = 0, ls = 3;                                                    \
        for (int c = 0; c < nchunks; c++) {                                    \
            if (c + 3 < nchunks) load_stage(ls, (c + 3) * BK);                 \
            else asm volatile("cp.async.commit_group;" ::: "memory");          \
            asm volatile("cp.async.wait_group 2;" ::: "memory");               \
            __syncthreads();                                                   \
            compute_stage(cs);                                                 \
            if (++cs == NSTAGE) cs = 0;                                        \
            if (++ls == NSTAGE) ls = 0;                                        \
        }                                                                      \
    }

// scalar epilogue
#define GEMM_EPI_SCALAR(P1, P2, SRC, DST, SBIAS, W2, B2, SOUT)                 \
    {                                                                          \
        float* sred = (float*)smem;                                            \
        _Pragma("unroll") for (int mi = 0; mi < 2; mi++)                       \
        _Pragma("unroll") for (int half = 0; half < 2; half++) {               \
            int rowl = wm * 32 + mi * 16 + half * 8 + (lane >> 2);             \
            int row = m0 + rowl;                                               \
            int cl = (row < M) ? row : (M - 1);                                \
            const __half* p1 = (P1) ? ((P1) + (size_t)(SRC)[cl] * 256) : nullptr;\
            const __half* p2 = (P2) ? ((P2) + (size_t)(DST)[cl] * 256) : nullptr;\
            float part = 0.f;                                                  \
            _Pragma("unroll") for (int nj = 0; nj < 16; nj++) {                \
                int col = wn * 128 + nj * 8 + (lane & 3) * 2;                  \
                float2 bv = *(const float2*)((SBIAS) + col);                   \
                float2 wv = *(const float2*)((W2) + col);                      \
                float2 p1v = make_float2(0.f, 0.f), p2v = make_float2(0.f, 0.f);\
                if (p1) p1v = __half22float2(*(const __half2*)(p1 + col));     \
                if (p2) p2v = __half22float2(*(const __half2*)(p2 + col));     \
                float v0 = fmaxf(acc[mi][nj][half * 2 + 0] + bv.x + p1v.x + p2v.x, 0.f);\
                float v1 = fmaxf(acc[mi][nj][half * 2 + 1] + bv.y + p1v.y + p2v.y, 0.f);\
                part = fmaf(v0, wv.x, part);                                   \
                part = fmaf(v1, wv.y, part);                                   \
            }                                                                  \
            part += __shfl_xor_sync(0xffffffffu, part, 1);                     \
            part += __shfl_xor_sync(0xffffffffu, part, 2);                     \
            if ((lane & 3) == 0) sred[rowl * 2 + wn] = part;                   \
        }                                                                      \
        __syncthreads();                                                       \
        if (tid < 128) {                                                       \
            int row = m0 + tid;                                                \
            if (row < M) (SOUT)[row] = sred[tid * 2] + sred[tid * 2 + 1] + (B2)[0];\
        }                                                                      \
    }

// ---------------- input projection GEMM (2-term exact-A) ----------------------
__global__ void __launch_bounds__(NTH, 1)
proj_gemm(const __half* __restrict__ A, const __half* __restrict__ AL,
          int M, int K, const __half* __restrict__ Bz,
          const float* __restrict__ bias, float* __restrict__ C,
          __half* __restrict__ ohh, __half* __restrict__ ohl)
{
    extern __shared__ char smem[];
    const uint32_t sb = smem_u32(smem);
    const int tid = threadIdx.x;
    const int lane = tid & 31;
    const int wid = tid >> 5;
    const int wm = wid & 3;
    const int wn = wid >> 2;
    const int m0 = blockIdx.x * BM;

    GEMM_MAINLOOP(true)

#pragma unroll
    for (int mi = 0; mi < 2; mi++) {
#pragma unroll
        for (int half = 0; half < 2; half++) {
            int row = m0 + wm * 32 + mi * 16 + half * 8 + (lane >> 2);
            if (row >= M) continue;
#pragma unroll
            for (int nj = 0; nj < 16; nj++) {
                int col = wn * 128 + nj * 8 + (lane & 3) * 2;
                float2 v;
                v.x = acc[mi][nj][half * 2 + 0] + bias[col];
                v.y = acc[mi][nj][half * 2 + 1] + bias[col + 1];
                *(float2*)(C + (size_t)row * 256 + col) = v;
                __half b0 = __float2half(v.x);
                __half b1 = __float2half(v.y);
                *(__half2*)(ohh + (size_t)row * 256 + col) = __half2(b0, b1);
                *(__half2*)(ohl + (size_t)row * 256 + col) =
                    __half2(__float2half(v.x - __half2float(b0)),
                            __float2half(v.y - __half2float(b1)));
            }
        }
    }
}

// ---------------- node GEMM: P1/P2 (1-term, fp16 out) --------------------------
__global__ void __launch_bounds__(NTH, 1)
node_gemm(const __half* __restrict__ A, int M, int K,
          const __half* __restrict__ Bh, __half* __restrict__ PC)
{
    extern __shared__ char smem[];
    const uint32_t sb = smem_u32(smem);
    const int tid = threadIdx.x;
    const int lane = tid & 31;
    const int wid = tid >> 5;
    const int wm = wid & 3;
    const int wn = wid >> 2;
    const int m0 = blockIdx.x * BM;
    const int z = blockIdx.z;
    const __half* AL = nullptr;
    const __half* Bz = Bh + (size_t)z * 65536;

    GEMM_MAINLOOP(false)

    __half* Pz = PC + (size_t)z * N_MAX * H;
#pragma unroll
    for (int mi = 0; mi < 2; mi++) {
#pragma unroll
        for (int half = 0; half < 2; half++) {
            int row = m0 + wm * 32 + mi * 16 + half * 8 + (lane >> 2);
            if (row >= M) continue;
#pragma unroll
            for (int nj = 0; nj < 16; nj++) {
                int col = wn * 128 + nj * 8 + (lane & 3) * 2;
                __half2 hp(__float2half(acc[mi][nj][half * 2 + 0]),
                           __float2half(acc[mi][nj][half * 2 + 1]));
                *(__half2*)(Pz + (size_t)row * 256 + col) = hp;
            }
        }
    }
}

// ---------------- edge + eps GEMM (1-term, flat 1D grid) -----------------------
__global__ void __launch_bounds__(NTH, 1)
edge_eps_gemm(const __half* __restrict__ Aedge, int E,
              const __half* __restrict__ Anode, int Nn, int nblkE,
              const __half* __restrict__ WhL,
              const float* __restrict__ a_b1, const float* __restrict__ a_w2,
              const float* __restrict__ a_b2, float* __restrict__ ae,
              const __half* __restrict__ P1, const __half* __restrict__ P2,
              const float* __restrict__ eps_b1, const float* __restrict__ eps_w2,
              const float* __restrict__ eps_b2, float* __restrict__ epsv)
{
    extern __shared__ char smem[];
    const uint32_t sb = smem_u32(smem);
    const int tid = threadIdx.x;
    const int lane = tid & 31;
    const int wid = tid >> 5;
    const int wm = wid & 3;
    const int wn = wid >> 2;
    const int bid = blockIdx.x;
    const int is_edge = (bid < nblkE);
    const int m0 = (is_edge ? bid : (bid - nblkE)) * BM;
    const int K = H;

    const __half* A = is_edge ? Aedge : Anode;
    const __half* AL = nullptr;
    const int M = is_edge ? E : Nn;
    const __half* Bz = WhL + (size_t)(is_edge ? 768 : 512) * 256;

    GEMM_MAINLOOP(false)

    if (is_edge) {
        GEMM_EPI_SCALAR(P1, P2, g_srcp, g_dstp, a_b1, a_w2, a_b2, ae)
    } else {
        GEMM_EPI_SCALAR((const __half*)nullptr, (const __half*)nullptr,
                        g_srcp, g_dstp, eps_b1, eps_w2, eps_b2, epsv)
    }
}

// ---------------- fused message + softmax + update (warp per node) -----------
// software-pipelined inner edge loop (depth 2)
__global__ void msg_update(const float* __restrict__ ae,
                           const __half* __restrict__ ghh,
                           const __half* __restrict__ hh_r,
                           const float* __restrict__ h_old,
                           const float* __restrict__ epsv,
                           float* __restrict__ h_new,
                           __half* __restrict__ hh_w, __half* __restrict__ hl_w,
                           int N)
{
    const int w = (blockIdx.x * blockDim.x + threadIdx.x) >> 5;
    const int lane = threadIdx.x & 31;
    if (w >= N) return;
    const int lo = g_off[w], hi = g_off[w + 1];

    float acc8[8];
#pragma unroll
    for (int q = 0; q < 8; q++) acc8[q] = 0.f;
    float s = 0.f;

    if (hi > lo) {
        float mym = -INFINITY;
        for (int j = lo + lane; j < hi; j += 32)
            mym = fmaxf(mym, ae[j]);
#pragma unroll
        for (int o = 16; o; o >>= 1)
            mym = fmaxf(mym, __shfl_xor_sync(0xffffffffu, mym, o));
        const float m = mym;
        for (int base = lo; base < hi; base += 32) {
            const int j = base + lane;
            int sr = 0;
            float c = 0.f;
            if (j < hi) {
                c = __expf(ae[j] - m);
                sr = g_srcp[j];
            }
            s += c;
            const int cnt = min(32, hi - base);
            // software pipeline: prefetch edge i+1 while fma'ing edge i
            float cc = __shfl_sync(0xffffffffu, c, 0);
            int ss = __shfl_sync(0xffffffffu, sr, 0);
            uint4 gv = *(const uint4*)(ghh + (size_t)base * H + lane * 8);
            uint4 hv = *(const uint4*)(hh_r + (size_t)ss * H + lane * 8);
            for (int i = 0; i < cnt; i++) {
                const float ci = cc;
                const uint4 g = gv, hq = hv;
                if (i + 1 < cnt) {
                    cc = __shfl_sync(0xffffffffu, c, i + 1);
                    int sn = __shfl_sync(0xffffffffu, sr, i + 1);
                    gv = *(const uint4*)(ghh + (size_t)(base + i + 1) * H + lane * 8);
                    hv = *(const uint4*)(hh_r + (size_t)sn * H + lane * 8);
                }
                float2 g0 = __half22float2(*(const __half2*)&g.x);
                float2 g1 = __half22float2(*(const __half2*)&g.y);
                float2 g2 = __half22float2(*(const __half2*)&g.z);
                float2 g3 = __half22float2(*(const __half2*)&g.w);
                float2 q0 = __half22float2(*(const __half2*)&hq.x);
                float2 q1 = __half22float2(*(const __half2*)&hq.y);
                float2 q2 = __half22float2(*(const __half2*)&hq.z);
                float2 q3 = __half22float2(*(const __half2*)&hq.w);
                acc8[0] = fmaf(ci * g0.x, q0.x, acc8[0]);
                acc8[1] = fmaf(ci * g0.y, q0.y, acc8[1]);
                acc8[2] = fmaf(ci * g1.x, q1.x, acc8[2]);
                acc8[3] = fmaf(ci * g1.y, q1.y, acc8[3]);
                acc8[4] = fmaf(ci * g2.x, q2.x, acc8[4]);
                acc8[5] = fmaf(ci * g2.y, q2.y, acc8[5]);
                acc8[6] = fmaf(ci * g3.x, q3.x, acc8[6]);
                acc8[7] = fmaf(ci * g3.y, q3.y, acc8[7]);
            }
        }
#pragma unroll
        for (int o = 16; o; o >>= 1)
            s += __shfl_xor_sync(0xffffffffu, s, o);
    }

    const float inv = (s > 0.f) ? (1.f / s) : 0.f;
    const float scale = (1.f + epsv[w]) * inv;

    const float4* hrow = (const float4*)(h_old + (size_t)w * H + lane * 8);
    float4 o0 = hrow[0], o1 = hrow[1];
    float4 r0, r1;
    r0.x = fmaf(acc8[0], scale, o0.x); r0.y = fmaf(acc8[1], scale, o0.y);
    r0.z = fmaf(acc8[2], scale, o0.z); r0.w = fmaf(acc8[3], scale, o0.w);
    r1.x = fmaf(acc8[4], scale, o1.x); r1.y = fmaf(acc8[5], scale, o1.y);
    r1.z = fmaf(acc8[6], scale, o1.z); r1.w = fmaf(acc8[7], scale, o1.w);
    float4* orow = (float4*)(h_new + (size_t)w * H + lane * 8);
    orow[0] = r0;
    orow[1] = r1;

    __half2 hp[4], lp[4];
    float vv[8] = {r0.x, r0.y, r0.z, r0.w, r1.x, r1.y, r1.z, r1.w};
#pragma unroll
    for (int q = 0; q < 4; q++) {
        __half b0 = __float2half(vv[q * 2]);
        __half b1 = __float2half(vv[q * 2 + 1]);
        hp[q] = __half2(b0, b1);
        lp[q] = __half2(__float2half(vv[q * 2] - __half2float(b0)),
                        __float2half(vv[q * 2 + 1] - __half2float(b1)));
    }
    *(uint4*)(hh_w + (size_t)w * H + lane * 8) = *(uint4*)hp;
    *(uint4*)(hl_w + (size_t)w * H + lane * 8) = *(uint4*)lp;
}

// ---------------- launch -------------------------------------------------------
extern "C" void kernel_launch(void* const* d_in, const int* in_sizes, int n_in,
                              void* d_out, int out_size)
{
    (void)n_in; (void)out_size;
    const float* node_feats = (const float*)d_in[0];
    const float* gh         = (const float*)d_in[1];
    const int*   src        = (const int*)d_in[2];
    const int*   dst        = (const int*)d_in[3];
    const float* Wn_w       = (const float*)d_in[4];
    const float* Wn_b       = (const float*)d_in[5];
    const float* eps_w1     = (const float*)d_in[6];
    const float* eps_b1     = (const float*)d_in[7];
    const float* eps_w2     = (const float*)d_in[8];
    const float* eps_b2     = (const float*)d_in[9];
    const float* a_w1       = (const float*)d_in[10];
    const float* a_b1       = (const float*)d_in[11];
    const float* a_w2       = (const float*)d_in[12];
    const float* a_b2       = (const float*)d_in[13];

    const int D_IN = 128;
    const int N = in_sizes[0] / D_IN;
    const int E = in_sizes[2];
    const int L = in_sizes[6] / (H * H);

    float* out = (float*)d_out;

    __half *ghh, *nfh, *nfl, *hh0, *hl0, *Wh, *wnh, *gP;
    float *epsv, *ae;
    cudaGetSymbolAddress((void**)&ghh, g_ghh);
    cudaGetSymbolAddress((void**)&nfh, g_nfh);
    cudaGetSymbolAddress((void**)&nfl, g_nfl);
    cudaGetSymbolAddress((void**)&hh0, g_hh);
    cudaGetSymbolAddress((void**)&hl0, g_hl);
    cudaGetSymbolAddress((void**)&Wh,  g_Wh);
    cudaGetSymbolAddress((void**)&wnh, g_wnh);
    cudaGetSymbolAddress((void**)&gP,   g_P);
    cudaGetSymbolAddress((void**)&epsv, g_eps);
    cudaGetSymbolAddress((void**)&ae,   g_ae);

    constexpr int SMEM2 = NSTAGE * (16384 + 16384);   // 2-term (proj) = 160KB
    constexpr int SMEM1 = NSTAGE * (8192 + 16384);    // 1-term = 120KB
    cudaFuncSetAttribute(proj_gemm, cudaFuncAttributeMaxDynamicSharedMemorySize, SMEM2);
    cudaFuncSetAttribute(node_gemm, cudaFuncAttributeMaxDynamicSharedMemorySize, SMEM1);
    cudaFuncSetAttribute(edge_eps_gemm, cudaFuncAttributeMaxDynamicSharedMemorySize, SMEM1);

    // one-time prep
    {
        int totw = L * 1024 * 256 + 128 * 256;
        prep_w<<<(totw + 255) / 256, 256>>>(a_w1, eps_w1, Wn_w, L, N);
        int n4 = (N * D_IN) / 4;
        int thr = (n4 > E) ? n4 : E;
        cvt_nf_hist<<<(thr + 255) / 256, 256>>>(node_feats, nfh, nfl, n4, dst, E);
        csr_scan<<<1, 1024>>>(N, E);
        csr_scatter<<<(E + 255) / 256, 256>>>(src, dst, E);
        int g4 = (E * H) / 4;
        cvt_gh_perm<<<(g4 + 255) / 256, 256>>>(gh, ghh, g4);
    }

    const int nblkN = (N + BM - 1) / BM;
    const int nblkE = (E + BM - 1) / BM;
    const size_t hbuf = (size_t)N_MAX * H;

    proj_gemm<<<dim3(nblkN, 1, 1), NTH, SMEM2>>>(
        nfh, nfl, N, D_IN, wnh, Wn_b, out, hh0, hl0);

    for (int l = 0; l < L; l++) {
        const float* hcur = out + (size_t)l * N * H;
        float*       hnext = out + (size_t)(l + 1) * N * H;
        const __half* WhL = Wh + (size_t)l * 1024 * 256;
        __half* hhr = hh0 + (size_t)(l & 1) * hbuf;
        __half* hhw = hh0 + (size_t)((l + 1) & 1) * hbuf;
        __half* hlw = hl0 + (size_t)((l + 1) & 1) * hbuf;

        node_gemm<<<dim3(nblkN, 1, 2), NTH, SMEM1>>>(hhr, N, H, WhL, gP);

        edge_eps_gemm<<<dim3(nblkE + nblkN, 1, 1), NTH, SMEM1>>>(
            ghh, E, hhr, N, nblkE, WhL,
            a_b1 + (size_t)l * H, a_w2 + (size_t)l * H, a_b2 + l, ae,
            gP, gP + hbuf,
            eps_b1 + (size_t)l * H, eps_w2 + (size_t)l * H, eps_b2 + l, epsv);

        msg_update<<<(N * 32 + 255) / 256, 256>>>(
            ae, ghh, hhr, hcur, epsv, hnext, hhw, hlw, N);
    }
}

// round 15
// speedup vs baseline: 1.0755x; 1.0755x over previous
#include <cuda_runtime.h>
#include <cuda_fp16.h>
#include <math.h>
#include <stdint.h>

#define H 256
#define N_MAX 10240
#define E_MAX 163840
#define L_MAX 3

#define BM 128
#define BN 256
#define NTH 256
#define NSTAGE 5     // BK=32 path (proj)
#define NST4 4       // BK=64 path (1-term)

// ---------------- scratch (device globals) ---------------------------------
__device__ __half g_ghh[E_MAX * H];            // gh fp16, PERMUTED by dst-sorted order
__device__ __half g_nfh[N_MAX * 128];
__device__ __half g_nfl[N_MAX * 128];
__device__ __half g_hh[2][N_MAX * H];
__device__ __half g_hl[2][N_MAX * H];
__device__ __half g_Wh[L_MAX * 1024 * 256];
__device__ __half g_wnh[128 * 256];
__device__ __half g_P[2 * N_MAX * H];
__device__ float g_eps[N_MAX];
__device__ float g_ae[E_MAX];
__device__ int g_cnt[N_MAX];
__device__ int g_off[N_MAX + 1];
__device__ int g_cur[N_MAX];
__device__ int g_perm[E_MAX];
__device__ int g_srcp[E_MAX];
__device__ int g_dstp[E_MAX];

// ---------------- helpers ----------------------------------------------------
__device__ __forceinline__ uint32_t smem_u32(const void* p) {
    uint32_t a;
    asm("{ .reg .u64 t; cvta.to.shared.u64 t, %1; cvt.u32.u64 %0, t; }" : "=r"(a) : "l"(p));
    return a;
}
__device__ __forceinline__ void cp16(uint32_t dst, const void* src) {
    asm volatile("cp.async.cg.shared.global [%0], [%1], 16;" :: "r"(dst), "l"(src));
}
__device__ __forceinline__ void ldsm4(uint32_t* r, uint32_t addr) {
    asm volatile("ldmatrix.sync.aligned.m8n8.x4.shared.b16 {%0,%1,%2,%3}, [%4];"
                 : "=r"(r[0]), "=r"(r[1]), "=r"(r[2]), "=r"(r[3]) : "r"(addr));
}
__device__ __forceinline__ void ldsm4t(uint32_t* r, uint32_t addr) {
    asm volatile("ldmatrix.sync.aligned.m8n8.x4.trans.shared.b16 {%0,%1,%2,%3}, [%4];"
                 : "=r"(r[0]), "=r"(r[1]), "=r"(r[2]), "=r"(r[3]) : "r"(addr));
}
__device__ __forceinline__ void mma16816(float* c, const uint32_t* a, const uint32_t* b) {
    asm volatile("mma.sync.aligned.m16n8k16.row.col.f32.f16.f16.f32 "
                 "{%0,%1,%2,%3}, {%4,%5,%6,%7}, {%8,%9}, {%0,%1,%2,%3};"
                 : "+f"(c[0]), "+f"(c[1]), "+f"(c[2]), "+f"(c[3])
                 : "r"(a[0]), "r"(a[1]), "r"(a[2]), "r"(a[3]), "r"(b[0]), "r"(b[1]));
}

// ---------------- weight prep (hi only) + csr clear ---------------------------
__global__ void prep_w(const float* __restrict__ a_w1, const float* __restrict__ eps_w1,
                       const float* __restrict__ Wn_w, int L, int N)
{
    const int totW = L * 1024 * 256;
    const int total = totW + 128 * 256;
    int idx = blockIdx.x * blockDim.x + threadIdx.x;
    if (idx < N) g_cnt[idx] = 0;
    if (idx >= total) return;
    float v;
    __half* dh;
    int di;
    if (idx < totW) {
        int l = idx / (1024 * 256);
        int r = (idx / 256) % 1024;
        int n = idx % 256;
        if (r < 512)      v = a_w1[((size_t)l * 768 + r) * 256 + n];
        else if (r < 768) v = eps_w1[((size_t)l * 256 + (r - 512)) * 256 + n];
        else              v = a_w1[((size_t)l * 768 + 512 + (r - 768)) * 256 + n];
        dh = g_Wh; di = idx;
    } else {
        int i2 = idx - totW;
        v = Wn_w[i2];
        dh = g_wnh; di = i2;
    }
    dh[di] = __float2half(v);
}

// ---------------- nf cvt (fp16 hi/lo) + csr_hist fused ------------------------
__global__ void cvt_nf_hist(const float* __restrict__ x, __half* __restrict__ hi,
                            __half* __restrict__ lo, int n4,
                            const int* __restrict__ dst, int E)
{
    int i = blockIdx.x * blockDim.x + threadIdx.x;
    if (i < E) atomicAdd(&g_cnt[dst[i]], 1);
    if (i >= n4) return;
    float4 v = ((const float4*)x)[i];
    __half h0 = __float2half(v.x), h1 = __float2half(v.y);
    __half h2 = __float2half(v.z), h3 = __float2half(v.w);
    ((__half2*)hi)[i * 2 + 0] = __half2(h0, h1);
    ((__half2*)hi)[i * 2 + 1] = __half2(h2, h3);
    ((__half2*)lo)[i * 2 + 0] = __half2(__float2half(v.x - __half2float(h0)),
                                        __float2half(v.y - __half2float(h1)));
    ((__half2*)lo)[i * 2 + 1] = __half2(__float2half(v.z - __half2float(h2)),
                                        __float2half(v.w - __half2float(h3)));
}

// ---------------- CSR scan (warp-shuffle two-level) ----------------------------
__global__ void csr_scan(int N, int E) {
    __shared__ int wsum[32];
    const int tid = threadIdx.x;
    const int lane = tid & 31;
    const int wrp = tid >> 5;
    const int chunk = (N + 1023) / 1024;
    const int base = tid * chunk;
    int s = 0;
#pragma unroll 4
    for (int i = 0; i < chunk; i++) {
        int idx = base + i;
        if (idx < N) s += g_cnt[idx];
    }
    int sc = s;
#pragma unroll
    for (int o = 1; o < 32; o <<= 1) {
        int v = __shfl_up_sync(0xffffffffu, sc, o);
        if (lane >= o) sc += v;
    }
    if (lane == 31) wsum[wrp] = sc;
    __syncthreads();
    if (wrp == 0) {
        int t = wsum[lane];
#pragma unroll
        for (int o = 1; o < 32; o <<= 1) {
            int v = __shfl_up_sync(0xffffffffu, t, o);
            if (lane >= o) t += v;
        }
        wsum[lane] = t;
    }
    __syncthreads();
    int run = sc - s + (wrp ? wsum[wrp - 1] : 0);
    for (int i = 0; i < chunk; i++) {
        int idx = base + i;
        if (idx < N) { g_off[idx] = run; g_cur[idx] = run; run += g_cnt[idx]; }
    }
    if (tid == 1023) g_off[N] = E;
}

__global__ void csr_scatter(const int* __restrict__ src, const int* __restrict__ dst,
                            int E)
{
    int e = blockIdx.x * blockDim.x + threadIdx.x;
    if (e < E) {
        int d = dst[e];
        int pos = atomicAdd(&g_cur[d], 1);
        g_perm[pos] = e;
        g_srcp[pos] = src[e];
        g_dstp[pos] = d;
    }
}

__global__ void cvt_gh_perm(const float* __restrict__ gh, __half* __restrict__ hi,
                            int n4)
{
    int i = blockIdx.x * blockDim.x + threadIdx.x;
    if (i >= n4) return;
    const int row = i >> 6;
    const int c4 = i & 63;
    const int e = g_perm[row];
    float4 v = ((const float4*)(gh + (size_t)e * H))[c4];
    __half2 hh0(__float2half(v.x), __float2half(v.y));
    __half2 hh1(__float2half(v.z), __float2half(v.w));
    ((__half2*)hi)[i * 2 + 0] = hh0;
    ((__half2*)hi)[i * 2 + 1] = hh1;
}

// ============ BK=32 mainloop (proj, 2-term) — R12-proven ======================
#define GEMM_MAINLOOP32(HAS_AL)                                                \
    constexpr uint32_t AH_OFF = 0;                                             \
    constexpr uint32_t AL_OFF = 8192;                                          \
    constexpr uint32_t BH_OFF = (HAS_AL) ? 16384u : 8192u;                     \
    constexpr uint32_t STB = BH_OFF + 16384u;                                  \
    float acc[2][16][4];                                                       \
    _Pragma("unroll") for (int mi = 0; mi < 2; mi++)                           \
    _Pragma("unroll") for (int nj = 0; nj < 16; nj++)                          \
    _Pragma("unroll") for (int q = 0; q < 4; q++) acc[mi][nj][q] = 0.f;        \
    const int nchunks = K / 32;                                                \
    auto load_stage = [&](int s, int k0) {                                     \
        const uint32_t base = sb + s * STB;                                    \
        _Pragma("unroll") for (int i = 0; i < 2; i++) {                        \
            int cid = tid + i * NTH;                                           \
            int row = cid >> 2;                                                \
            int cb = (cid & 3) * 16;                                           \
            int grow = m0 + row;                                               \
            if (grow >= M) grow = M - 1;                                       \
            size_t gb = ((size_t)grow * K + k0) * 2 + cb;                      \
            uint32_t d = base + row * 64 + (cb ^ ((row & 3) << 4));            \
            cp16(d + AH_OFF, (const char*)A + gb);                             \
            if (HAS_AL) cp16(d + AL_OFF, (const char*)AL + gb);                \
        }                                                                      \
        _Pragma("unroll") for (int i = 0; i < 4; i++) {                        \
            int cid = tid + i * NTH;                                           \
            int k = cid >> 5;                                                  \
            int cb = (cid & 31) * 16;                                          \
            size_t gb = (size_t)(k0 + k) * 512 + cb;                           \
            uint32_t d = base + k * 512 + (cb ^ ((k & 7) << 4));               \
            cp16(d + BH_OFF, (const char*)Bz + gb);                            \
        }                                                                      \
        asm volatile("cp.async.commit_group;" ::: "memory");                   \
    };                                                                         \
    auto compute_stage = [&](int s) {                                          \
        const uint32_t base = sb + s * STB;                                    \
        _Pragma("unroll") for (int kk = 0; kk < 2; kk++) {                     \
            uint32_t ah[2][4], al[2][4];                                       \
            _Pragma("unroll") for (int mi = 0; mi < 2; mi++) {                 \
                int row = wm * 32 + mi * 16 + (lane & 15);                     \
                uint32_t cb = kk * 32 + ((lane >> 4) << 4);                    \
                uint32_t ad = base + row * 64 + (cb ^ ((row & 3) << 4));       \
                ldsm4(ah[mi], ad + AH_OFF);                                    \
                if (HAS_AL) ldsm4(al[mi], ad + AL_OFF);                        \
            }                                                                  \
            const int kr = kk * 16 + (lane & 15);                              \
            const uint32_t hi16 = (lane >> 4) << 4;                            \
            uint32_t bhA[4], bhB[4];                                           \
            {                                                                  \
                uint32_t cb = wn * 256 + hi16;                                 \
                uint32_t bd = base + kr * 512 + (cb ^ ((kr & 7) << 4));        \
                ldsm4t(bhA, bd + BH_OFF);                                      \
            }                                                                  \
            _Pragma("unroll") for (int nj2 = 0; nj2 < 8; nj2++) {              \
                uint32_t* ch = (nj2 & 1) ? bhB : bhA;                          \
                if (nj2 < 7) {                                                 \
                    uint32_t* nh = (nj2 & 1) ? bhA : bhB;                      \
                    uint32_t cb = wn * 256 + (nj2 + 1) * 32 + hi16;            \
                    uint32_t bd = base + kr * 512 + (cb ^ ((kr & 7) << 4));    \
                    ldsm4t(nh, bd + BH_OFF);                                   \
                }                                                              \
                _Pragma("unroll") for (int mi = 0; mi < 2; mi++)               \
                _Pragma("unroll") for (int sub = 0; sub < 2; sub++) {          \
                    int nj = nj2 * 2 + sub;                                    \
                    mma16816(acc[mi][nj], ah[mi], &ch[sub * 2]);               \
                    if (HAS_AL) mma16816(acc[mi][nj], al[mi], &ch[sub * 2]);   \
                }                                                              \
            }                                                                  \
        }                                                                      \
    };                                                                         \
    for (int p = 0; p < 3 && p < nchunks; p++) load_stage(p, p * 32);          \
    {                                                                          \
        int cs = 0, ls = 3;                                                    \
        for (int c = 0; c < nchunks; c++) {                                    \
            if (c + 3 < nchunks) load_stage(ls, (c + 3) * 32);                 \
            else asm volatile("cp.async.commit_group;" ::: "memory");          \
            asm volatile("cp.async.wait_group 2;" ::: "memory");               \
            __syncthreads();                                                   \
            compute_stage(cs);                                                 \
            if (++cs == NSTAGE) cs = 0;                                        \
            if (++ls == NSTAGE) ls = 0;                                        \
        }                                                                      \
    }

// ============ BK=64 mainloop (1-term) — 4 chunks for K=256, half the barriers ==
// Stage: A 128x128B (SW128) = 16KB at 0, B 64x512B = 32KB at 16KB. 4 stages.
#define GEMM_MAINLOOP64()                                                      \
    constexpr uint32_t BH_OFF = 16384u;                                        \
    constexpr uint32_t STB = 49152u;                                           \
    float acc[2][16][4];                                                       \
    _Pragma("unroll") for (int mi = 0; mi < 2; mi++)                           \
    _Pragma("unroll") for (int nj = 0; nj < 16; nj++)                          \
    _Pragma("unroll") for (int q = 0; q < 4; q++) acc[mi][nj][q] = 0.f;        \
    const int nchunks = K / 64;                                                \
    auto load_stage = [&](int s, int k0) {                                     \
        const uint32_t base = sb + s * STB;                                    \
        _Pragma("unroll") for (int i = 0; i < 4; i++) {                        \
            int cid = tid + i * NTH;                                           \
            int row = cid >> 3;                                                \
            int cb = (cid & 7) * 16;                                           \
            int grow = m0 + row;                                               \
            if (grow >= M) grow = M - 1;                                       \
            size_t gb = ((size_t)grow * K + k0) * 2 + cb;                      \
            uint32_t d = base + row * 128 + (cb ^ ((row & 7) << 4));           \
            cp16(d, (const char*)A + gb);                                      \
        }                                                                      \
        _Pragma("unroll") for (int i = 0; i < 8; i++) {                        \
            int cid = tid + i * NTH;                                           \
            int k = cid >> 5;                                                  \
            int cb = (cid & 31) * 16;                                          \
            size_t gb = (size_t)(k0 + k) * 512 + cb;                           \
            uint32_t d = base + k * 512 + (cb ^ ((k & 7) << 4));               \
            cp16(d + BH_OFF, (const char*)Bz + gb);                            \
        }                                                                      \
        asm volatile("cp.async.commit_group;" ::: "memory");                   \
    };                                                                         \
    auto compute_stage = [&](int s) {                                          \
        const uint32_t base = sb + s * STB;                                    \
        _Pragma("unroll") for (int kk = 0; kk < 4; kk++) {                     \
            uint32_t ah[2][4];                                                 \
            _Pragma("unroll") for (int mi = 0; mi < 2; mi++) {                 \
                int row = wm * 32 + mi * 16 + (lane & 15);                     \
                uint32_t cb = kk * 32 + ((lane >> 4) << 4);                    \
                uint32_t ad = base + row * 128 + (cb ^ ((row & 7) << 4));      \
                ldsm4(ah[mi], ad);                                             \
            }                                                                  \
            const int kr = kk * 16 + (lane & 15);                              \
            const uint32_t hi16 = (lane >> 4) << 4;                            \
            uint32_t bhA[4], bhB[4];                                           \
            {                                                                  \
                uint32_t cb = wn * 256 + hi16;                                 \
                uint32_t bd = base + kr * 512 + (cb ^ ((kr & 7) << 4));        \
                ldsm4t(bhA, bd + BH_OFF);                                      \
            }                                                                  \
            _Pragma("unroll") for (int nj2 = 0; nj2 < 8; nj2++) {              \
                uint32_t* ch = (nj2 & 1) ? bhB : bhA;                          \
                if (nj2 < 7) {                                                 \
                    uint32_t* nh = (nj2 & 1) ? bhA : bhB;                      \
                    uint32_t cb = wn * 256 + (nj2 + 1) * 32 + hi16;            \
                    uint32_t bd = base + kr * 512 + (cb ^ ((kr & 7) << 4));    \
                    ldsm4t(nh, bd + BH_OFF);                                   \
                }                                                              \
                _Pragma("unroll") for (int mi = 0; mi < 2; mi++)               \
                _Pragma("unroll") for (int sub = 0; sub < 2; sub++) {          \
                    int nj = nj2 * 2 + sub;                                    \
                    mma16816(acc[mi][nj], ah[mi], &ch[sub * 2]);               \
                }                                                              \
            }                                                                  \
        }                                                                      \
    };                                                                         \
    for (int p = 0; p < 3 && p < nchunks; p++) load_stage(p, p * 64);          \
    {                                                                          \
        int cs = 0, ls = 3;                                                    \
        for (int c = 0; c < nchunks; c++) {                                    \
            if (c + 3 < nchunks) load_stage(ls, (c + 3) * 64);                 \
            else asm volatile("cp.async.commit_group;" ::: "memory");          \
            asm volatile("cp.async.wait_group 2;" ::: "memory");               \
            __syncthreads();                                                   \
            compute_stage(cs);                                                 \
            if (++cs == NST4) cs = 0;                                          \
            if (++ls == NST4) ls = 0;                                          \
        }                                                                      \
    }

// scalar epilogue (R12)
#define GEMM_EPI_SCALAR(P1, P2, SRC, DST, SBIAS, W2, B2, SOUT)                 \
    {                                                                          \
        float* sred = (float*)smem;                                            \
        _Pragma("unroll") for (int mi = 0; mi < 2; mi++)                       \
        _Pragma("unroll") for (int half = 0; half < 2; half++) {               \
            int rowl = wm * 32 + mi * 16 + half * 8 + (lane >> 2);             \
            int row = m0 + rowl;                                               \
            int cl = (row < M) ? row : (M - 1);                                \
            const __half* p1 = (P1) ? ((P1) + (size_t)(SRC)[cl] * 256) : nullptr;\
            const __half* p2 = (P2) ? ((P2) + (size_t)(DST)[cl] * 256) : nullptr;\
            float part = 0.f;                                                  \
            _Pragma("unroll") for (int nj = 0; nj < 16; nj++) {                \
                int col = wn * 128 + nj * 8 + (lane & 3) * 2;                  \
                float2 bv = *(const float2*)((SBIAS) + col);                   \
                float2 wv = *(const float2*)((W2) + col);                      \
                float2 p1v = make_float2(0.f, 0.f), p2v = make_float2(0.f, 0.f);\
                if (p1) p1v = __half22float2(*(const __half2*)(p1 + col));     \
                if (p2) p2v = __half22float2(*(const __half2*)(p2 + col));     \
                float v0 = fmaxf(acc[mi][nj][half * 2 + 0] + bv.x + p1v.x + p2v.x, 0.f);\
                float v1 = fmaxf(acc[mi][nj][half * 2 + 1] + bv.y + p1v.y + p2v.y, 0.f);\
                part = fmaf(v0, wv.x, part);                                   \
                part = fmaf(v1, wv.y, part);                                   \
            }                                                                  \
            part += __shfl_xor_sync(0xffffffffu, part, 1);                     \
            part += __shfl_xor_sync(0xffffffffu, part, 2);                     \
            if ((lane & 3) == 0) sred[rowl * 2 + wn] = part;                   \
        }                                                                      \
        __syncthreads();                                                       \
        if (tid < 128) {                                                       \
            int row = m0 + tid;                                                \
            if (row < M) (SOUT)[row] = sred[tid * 2] + sred[tid * 2 + 1] + (B2)[0];\
        }                                                                      \
    }

// ---------------- input projection GEMM (2-term exact-A, BK=32) ---------------
__global__ void __launch_bounds__(NTH, 1)
proj_gemm(const __half* __restrict__ A, const __half* __restrict__ AL,
          int M, int K, const __half* __restrict__ Bz,
          const float* __restrict__ bias, float* __restrict__ C,
          __half* __restrict__ ohh, __half* __restrict__ ohl)
{
    extern __shared__ char smem[];
    const uint32_t sb = smem_u32(smem);
    const int tid = threadIdx.x;
    const int lane = tid & 31;
    const int wid = tid >> 5;
    const int wm = wid & 3;
    const int wn = wid >> 2;
    const int m0 = blockIdx.x * BM;

    GEMM_MAINLOOP32(true)

#pragma unroll
    for (int mi = 0; mi < 2; mi++) {
#pragma unroll
        for (int half = 0; half < 2; half++) {
            int row = m0 + wm * 32 + mi * 16 + half * 8 + (lane >> 2);
            if (row >= M) continue;
#pragma unroll
            for (int nj = 0; nj < 16; nj++) {
                int col = wn * 128 + nj * 8 + (lane & 3) * 2;
                float2 v;
                v.x = acc[mi][nj][half * 2 + 0] + bias[col];
                v.y = acc[mi][nj][half * 2 + 1] + bias[col + 1];
                *(float2*)(C + (size_t)row * 256 + col) = v;
                __half b0 = __float2half(v.x);
                __half b1 = __float2half(v.y);
                *(__half2*)(ohh + (size_t)row * 256 + col) = __half2(b0, b1);
                *(__half2*)(ohl + (size_t)row * 256 + col) =
                    __half2(__float2half(v.x - __half2float(b0)),
                            __float2half(v.y - __half2float(b1)));
            }
        }
    }
}

// ---------------- node GEMM: P1/P2 (1-term, BK=64, fp16 out) -------------------
__global__ void __launch_bounds__(NTH, 1)
node_gemm(const __half* __restrict__ A, int M, int K,
          const __half* __restrict__ Bh, __half* __restrict__ PC)
{
    extern __shared__ char smem[];
    const uint32_t sb = smem_u32(smem);
    const int tid = threadIdx.x;
    const int lane = tid & 31;
    const int wid = tid >> 5;
    const int wm = wid & 3;
    const int wn = wid >> 2;
    const int m0 = blockIdx.x * BM;
    const int z = blockIdx.z;
    const __half* Bz = Bh + (size_t)z * 65536;

    GEMM_MAINLOOP64()

    __half* Pz = PC + (size_t)z * N_MAX * H;
#pragma unroll
    for (int mi = 0; mi < 2; mi++) {
#pragma unroll
        for (int half = 0; half < 2; half++) {
            int row = m0 + wm * 32 + mi * 16 + half * 8 + (lane >> 2);
            if (row >= M) continue;
#pragma unroll
            for (int nj = 0; nj < 16; nj++) {
                int col = wn * 128 + nj * 8 + (lane & 3) * 2;
                __half2 hp(__float2half(acc[mi][nj][half * 2 + 0]),
                           __float2half(acc[mi][nj][half * 2 + 1]));
                *(__half2*)(Pz + (size_t)row * 256 + col) = hp;
            }
        }
    }
}

// ---------------- edge + eps GEMM (1-term, BK=64, flat 1D grid) ----------------
__global__ void __launch_bounds__(NTH, 1)
edge_eps_gemm(const __half* __restrict__ Aedge, int E,
              const __half* __restrict__ Anode, int Nn, int nblkE,
              const __half* __restrict__ WhL,
              const float* __restrict__ a_b1, const float* __restrict__ a_w2,
              const float* __restrict__ a_b2, float* __restrict__ ae,
              const __half* __restrict__ P1, const __half* __restrict__ P2,
              const float* __restrict__ eps_b1, const float* __restrict__ eps_w2,
              const float* __restrict__ eps_b2, float* __restrict__ epsv)
{
    extern __shared__ char smem[];
    const uint32_t sb = smem_u32(smem);
    const int tid = threadIdx.x;
    const int lane = tid & 31;
    const int wid = tid >> 5;
    const int wm = wid & 3;
    const int wn = wid >> 2;
    const int bid = blockIdx.x;
    const int is_edge = (bid < nblkE);
    const int m0 = (is_edge ? bid : (bid - nblkE)) * BM;
    const int K = H;

    const __half* A = is_edge ? Aedge : Anode;
    const int M = is_edge ? E : Nn;
    const __half* Bz = WhL + (size_t)(is_edge ? 768 : 512) * 256;

    GEMM_MAINLOOP64()

    if (is_edge) {
        GEMM_EPI_SCALAR(P1, P2, g_srcp, g_dstp, a_b1, a_w2, a_b2, ae)
    } else {
        GEMM_EPI_SCALAR((const __half*)nullptr, (const __half*)nullptr,
                        g_srcp, g_dstp, eps_b1, eps_w2, eps_b2, epsv)
    }
}

// ---------------- fused message + softmax + update (R12 version) --------------
__global__ void msg_update(const float* __restrict__ ae,
                           const __half* __restrict__ ghh,
                           const __half* __restrict__ hh_r,
                           const float* __restrict__ h_old,
                           const float* __restrict__ epsv,
                           float* __restrict__ h_new,
                           __half* __restrict__ hh_w, __half* __restrict__ hl_w,
                           int N)
{
    const int w = (blockIdx.x * blockDim.x + threadIdx.x) >> 5;
    const int lane = threadIdx.x & 31;
    if (w >= N) return;
    const int lo = g_off[w], hi = g_off[w + 1];

    float acc8[8];
#pragma unroll
    for (int q = 0; q < 8; q++) acc8[q] = 0.f;
    float s = 0.f;

    if (hi > lo) {
        float mym = -INFINITY;
        for (int j = lo + lane; j < hi; j += 32)
            mym = fmaxf(mym, ae[j]);
#pragma unroll
        for (int o = 16; o; o >>= 1)
            mym = fmaxf(mym, __shfl_xor_sync(0xffffffffu, mym, o));
        const float m = mym;
        for (int base = lo; base < hi; base += 32) {
            const int j = base + lane;
            int sr = 0;
            float c = 0.f;
            if (j < hi) {
                c = __expf(ae[j] - m);
                sr = g_srcp[j];
            }
            s += c;
            const int cnt = min(32, hi - base);
            for (int i = 0; i < cnt; i++) {
                const float ci = __shfl_sync(0xffffffffu, c, i);
                const int si = __shfl_sync(0xffffffffu, sr, i);
                const int ji = base + i;
                const uint4 gv = *(const uint4*)(ghh + (size_t)ji * H + lane * 8);
                const uint4 hv16 = *(const uint4*)(hh_r + (size_t)si * H + lane * 8);
                float2 g0 = __half22float2(*(const __half2*)&gv.x);
                float2 g1 = __half22float2(*(const __half2*)&gv.y);
                float2 g2 = __half22float2(*(const __half2*)&gv.z);
                float2 g3 = __half22float2(*(const __half2*)&gv.w);
                float2 q0 = __half22float2(*(const __half2*)&hv16.x);
                float2 q1 = __half22float2(*(const __half2*)&hv16.y);
                float2 q2 = __half22float2(*(const __half2*)&hv16.z);
                float2 q3 = __half22float2(*(const __half2*)&hv16.w);
                acc8[0] = fmaf(ci * g0.x, q0.x, acc8[0]);
                acc8[1] = fmaf(ci * g0.y, q0.y, acc8[1]);
                acc8[2] = fmaf(ci * g1.x, q1.x, acc8[2]);
                acc8[3] = fmaf(ci * g1.y, q1.y, acc8[3]);
                acc8[4] = fmaf(ci * g2.x, q2.x, acc8[4]);
                acc8[5] = fmaf(ci * g2.y, q2.y, acc8[5]);
                acc8[6] = fmaf(ci * g3.x, q3.x, acc8[6]);
                acc8[7] = fmaf(ci * g3.y, q3.y, acc8[7]);
            }
        }
#pragma unroll
        for (int o = 16; o; o >>= 1)
            s += __shfl_xor_sync(0xffffffffu, s, o);
    }

    const float inv = (s > 0.f) ? (1.f / s) : 0.f;
    const float scale = (1.f + epsv[w]) * inv;

    const float4* hrow = (const float4*)(h_old + (size_t)w * H + lane * 8);
    float4 o0 = hrow[0], o1 = hrow[1];
    float4 r0, r1;
    r0.x = fmaf(acc8[0], scale, o0.x); r0.y = fmaf(acc8[1], scale, o0.y);
    r0.z = fmaf(acc8[2], scale, o0.z); r0.w = fmaf(acc8[3], scale, o0.w);
    r1.x = fmaf(acc8[4], scale, o1.x); r1.y = fmaf(acc8[5], scale, o1.y);
    r1.z = fmaf(acc8[6], scale, o1.z); r1.w = fmaf(acc8[7], scale, o1.w);
    float4* orow = (float4*)(h_new + (size_t)w * H + lane * 8);
    orow[0] = r0;
    orow[1] = r1;

    __half2 hp[4], lp[4];
    float vv[8] = {r0.x, r0.y, r0.z, r0.w, r1.x, r1.y, r1.z, r1.w};
#pragma unroll
    for (int q = 0; q < 4; q++) {
        __half b0 = __float2half(vv[q * 2]);
        __half b1 = __float2half(vv[q * 2 + 1]);
        hp[q] = __half2(b0, b1);
        lp[q] = __half2(__float2half(vv[q * 2] - __half2float(b0)),
                        __float2half(vv[q * 2 + 1] - __half2float(b1)));
    }
    *(uint4*)(hh_w + (size_t)w * H + lane * 8) = *(uint4*)hp;
    *(uint4*)(hl_w + (size_t)w * H + lane * 8) = *(uint4*)lp;
}

// ---------------- launch -------------------------------------------------------
extern "C" void kernel_launch(void* const* d_in, const int* in_sizes, int n_in,
                              void* d_out, int out_size)
{
    (void)n_in; (void)out_size;
    const float* node_feats = (const float*)d_in[0];
    const float* gh         = (const float*)d_in[1];
    const int*   src        = (const int*)d_in[2];
    const int*   dst        = (const int*)d_in[3];
    const float* Wn_w       = (const float*)d_in[4];
    const float* Wn_b       = (const float*)d_in[5];
    const float* eps_w1     = (const float*)d_in[6];
    const float* eps_b1     = (const float*)d_in[7];
    const float* eps_w2     = (const float*)d_in[8];
    const float* eps_b2     = (const float*)d_in[9];
    const float* a_w1       = (const float*)d_in[10];
    const float* a_b1       = (const float*)d_in[11];
    const float* a_w2       = (const float*)d_in[12];
    const float* a_b2       = (const float*)d_in[13];

    const int D_IN = 128;
    const int N = in_sizes[0] / D_IN;
    const int E = in_sizes[2];
    const int L = in_sizes[6] / (H * H);

    float* out = (float*)d_out;

    __half *ghh, *nfh, *nfl, *hh0, *hl0, *Wh, *wnh, *gP;
    float *epsv, *ae;
    cudaGetSymbolAddress((void**)&ghh, g_ghh);
    cudaGetSymbolAddress((void**)&nfh, g_nfh);
    cudaGetSymbolAddress((void**)&nfl, g_nfl);
    cudaGetSymbolAddress((void**)&hh0, g_hh);
    cudaGetSymbolAddress((void**)&hl0, g_hl);
    cudaGetSymbolAddress((void**)&Wh,  g_Wh);
    cudaGetSymbolAddress((void**)&wnh, g_wnh);
    cudaGetSymbolAddress((void**)&gP,   g_P);
    cudaGetSymbolAddress((void**)&epsv, g_eps);
    cudaGetSymbolAddress((void**)&ae,   g_ae);

    constexpr int SMEM2 = NSTAGE * (16384 + 16384);   // proj (BK=32, 2-term) = 160KB
    constexpr int SMEM64 = NST4 * 49152;              // 1-term BK=64 = 192KB
    cudaFuncSetAttribute(proj_gemm, cudaFuncAttributeMaxDynamicSharedMemorySize, SMEM2);
    cudaFuncSetAttribute(node_gemm, cudaFuncAttributeMaxDynamicSharedMemorySize, SMEM64);
    cudaFuncSetAttribute(edge_eps_gemm, cudaFuncAttributeMaxDynamicSharedMemorySize, SMEM64);

    // one-time prep
    {
        int totw = L * 1024 * 256 + 128 * 256;
        prep_w<<<(totw + 255) / 256, 256>>>(a_w1, eps_w1, Wn_w, L, N);
        int n4 = (N * D_IN) / 4;
        int thr = (n4 > E) ? n4 : E;
        cvt_nf_hist<<<(thr + 255) / 256, 256>>>(node_feats, nfh, nfl, n4, dst, E);
        csr_scan<<<1, 1024>>>(N, E);
        csr_scatter<<<(E + 255) / 256, 256>>>(src, dst, E);
        int g4 = (E * H) / 4;
        cvt_gh_perm<<<(g4 + 255) / 256, 256>>>(gh, ghh, g4);
    }

    const int nblkN = (N + BM - 1) / BM;
    const int nblkE = (E + BM - 1) / BM;
    const size_t hbuf = (size_t)N_MAX * H;

    proj_gemm<<<dim3(nblkN, 1, 1), NTH, SMEM2>>>(
        nfh, nfl, N, D_IN, wnh, Wn_b, out, hh0, hl0);

    for (int l = 0; l < L; l++) {
        const float* hcur = out + (size_t)l * N * H;
        float*       hnext = out + (size_t)(l + 1) * N * H;
        const __half* WhL = Wh + (size_t)l * 1024 * 256;
        __half* hhr = hh0 + (size_t)(l & 1) * hbuf;
        __half* hhw = hh0 + (size_t)((l + 1) & 1) * hbuf;
        __half* hlw = hl0 + (size_t)((l + 1) & 1) * hbuf;

        node_gemm<<<dim3(nblkN, 1, 2), NTH, SMEM64>>>(hhr, N, H, WhL, gP);

        edge_eps_gemm<<<dim3(nblkE + nblkN, 1, 1), NTH, SMEM64>>>(
            ghh, E, hhr, N, nblkE, WhL,
            a_b1 + (size_t)l * H, a_w2 + (size_t)l * H, a_b2 + l, ae,
            gP, gP + hbuf,
            eps_b1 + (size_t)l * H, eps_w2 + (size_t)l * H, eps_b2 + l, epsv);

        msg_update<<<(N * 32 + 255) / 256, 256>>>(
            ae, ghh, hhr, hcur, epsv, hnext, hhw, hlw, N);
    }
}

// round 16
// speedup vs baseline: 1.0885x; 1.0120x over previous
#include <cuda_runtime.h>
#include <cuda_fp16.h>
#include <math.h>
#include <stdint.h>

#define H 256
#define N_MAX 10240
#define E_MAX 163840
#define L_MAX 3

#define BM 128
#define BN 256
#define NTH 256
#define NSTAGE 5     // BK=32 path (proj)

// ---------------- scratch (device globals) ---------------------------------
__device__ __half g_ghh[E_MAX * H];            // gh fp16, PERMUTED by dst-sorted order
__device__ __half g_nfh[N_MAX * 128];
__device__ __half g_nfl[N_MAX * 128];
__device__ __half g_hh[2][N_MAX * H];
__device__ __half g_hl[2][N_MAX * H];
__device__ __half g_Wh[L_MAX * 1024 * 256];
__device__ __half g_wnh[128 * 256];
__device__ __half g_P[2 * N_MAX * H];
__device__ float g_eps[N_MAX];
__device__ float g_ae[E_MAX];
__device__ int g_cnt[N_MAX];
__device__ int g_off[N_MAX + 1];
__device__ int g_cur[N_MAX];
__device__ int g_perm[E_MAX];
__device__ int g_srcp[E_MAX];
__device__ int g_dstp[E_MAX];

// ---------------- helpers ----------------------------------------------------
__device__ __forceinline__ uint32_t smem_u32(const void* p) {
    uint32_t a;
    asm("{ .reg .u64 t; cvta.to.shared.u64 t, %1; cvt.u32.u64 %0, t; }" : "=r"(a) : "l"(p));
    return a;
}
__device__ __forceinline__ void cp16(uint32_t dst, const void* src) {
    asm volatile("cp.async.cg.shared.global [%0], [%1], 16;" :: "r"(dst), "l"(src));
}
__device__ __forceinline__ void ldsm4(uint32_t* r, uint32_t addr) {
    asm volatile("ldmatrix.sync.aligned.m8n8.x4.shared.b16 {%0,%1,%2,%3}, [%4];"
                 : "=r"(r[0]), "=r"(r[1]), "=r"(r[2]), "=r"(r[3]) : "r"(addr));
}
__device__ __forceinline__ void ldsm4t(uint32_t* r, uint32_t addr) {
    asm volatile("ldmatrix.sync.aligned.m8n8.x4.trans.shared.b16 {%0,%1,%2,%3}, [%4];"
                 : "=r"(r[0]), "=r"(r[1]), "=r"(r[2]), "=r"(r[3]) : "r"(addr));
}
__device__ __forceinline__ void mma16816(float* c, const uint32_t* a, const uint32_t* b) {
    asm volatile("mma.sync.aligned.m16n8k16.row.col.f32.f16.f16.f32 "
                 "{%0,%1,%2,%3}, {%4,%5,%6,%7}, {%8,%9}, {%0,%1,%2,%3};"
                 : "+f"(c[0]), "+f"(c[1]), "+f"(c[2]), "+f"(c[3])
                 : "r"(a[0]), "r"(a[1]), "r"(a[2]), "r"(a[3]), "r"(b[0]), "r"(b[1]));
}

// ---------------- weight prep (hi only) + csr clear ---------------------------
__global__ void prep_w(const float* __restrict__ a_w1, const float* __restrict__ eps_w1,
                       const float* __restrict__ Wn_w, int L, int N)
{
    const int totW = L * 1024 * 256;
    const int total = totW + 128 * 256;
    int idx = blockIdx.x * blockDim.x + threadIdx.x;
    if (idx < N) g_cnt[idx] = 0;
    if (idx >= total) return;
    float v;
    __half* dh;
    int di;
    if (idx < totW) {
        int l = idx / (1024 * 256);
        int r = (idx / 256) % 1024;
        int n = idx % 256;
        if (r < 512)      v = a_w1[((size_t)l * 768 + r) * 256 + n];
        else if (r < 768) v = eps_w1[((size_t)l * 256 + (r - 512)) * 256 + n];
        else              v = a_w1[((size_t)l * 768 + 512 + (r - 768)) * 256 + n];
        dh = g_Wh; di = idx;
    } else {
        int i2 = idx - totW;
        v = Wn_w[i2];
        dh = g_wnh; di = i2;
    }
    dh[di] = __float2half(v);
}

// ---------------- nf cvt (fp16 hi/lo) + csr_hist fused ------------------------
__global__ void cvt_nf_hist(const float* __restrict__ x, __half* __restrict__ hi,
                            __half* __restrict__ lo, int n4,
                            const int* __restrict__ dst, int E)
{
    int i = blockIdx.x * blockDim.x + threadIdx.x;
    if (i < E) atomicAdd(&g_cnt[dst[i]], 1);
    if (i >= n4) return;
    float4 v = ((const float4*)x)[i];
    __half h0 = __float2half(v.x), h1 = __float2half(v.y);
    __half h2 = __float2half(v.z), h3 = __float2half(v.w);
    ((__half2*)hi)[i * 2 + 0] = __half2(h0, h1);
    ((__half2*)hi)[i * 2 + 1] = __half2(h2, h3);
    ((__half2*)lo)[i * 2 + 0] = __half2(__float2half(v.x - __half2float(h0)),
                                        __float2half(v.y - __half2float(h1)));
    ((__half2*)lo)[i * 2 + 1] = __half2(__float2half(v.z - __half2float(h2)),
                                        __float2half(v.w - __half2float(h3)));
}

// ---------------- CSR scan (warp-shuffle two-level) ----------------------------
__global__ void csr_scan(int N, int E) {
    __shared__ int wsum[32];
    const int tid = threadIdx.x;
    const int lane = tid & 31;
    const int wrp = tid >> 5;
    const int chunk = (N + 1023) / 1024;
    const int base = tid * chunk;
    int s = 0;
#pragma unroll 4
    for (int i = 0; i < chunk; i++) {
        int idx = base + i;
        if (idx < N) s += g_cnt[idx];
    }
    int sc = s;
#pragma unroll
    for (int o = 1; o < 32; o <<= 1) {
        int v = __shfl_up_sync(0xffffffffu, sc, o);
        if (lane >= o) sc += v;
    }
    if (lane == 31) wsum[wrp] = sc;
    __syncthreads();
    if (wrp == 0) {
        int t = wsum[lane];
#pragma unroll
        for (int o = 1; o < 32; o <<= 1) {
            int v = __shfl_up_sync(0xffffffffu, t, o);
            if (lane >= o) t += v;
        }
        wsum[lane] = t;
    }
    __syncthreads();
    int run = sc - s + (wrp ? wsum[wrp - 1] : 0);
    for (int i = 0; i < chunk; i++) {
        int idx = base + i;
        if (idx < N) { g_off[idx] = run; g_cur[idx] = run; run += g_cnt[idx]; }
    }
    if (tid == 1023) g_off[N] = E;
}

__global__ void csr_scatter(const int* __restrict__ src, const int* __restrict__ dst,
                            int E)
{
    int e = blockIdx.x * blockDim.x + threadIdx.x;
    if (e < E) {
        int d = dst[e];
        int pos = atomicAdd(&g_cur[d], 1);
        g_perm[pos] = e;
        g_srcp[pos] = src[e];
        g_dstp[pos] = d;
    }
}

__global__ void cvt_gh_perm(const float* __restrict__ gh, __half* __restrict__ hi,
                            int n4)
{
    int i = blockIdx.x * blockDim.x + threadIdx.x;
    if (i >= n4) return;
    const int row = i >> 6;
    const int c4 = i & 63;
    const int e = g_perm[row];
    float4 v = ((const float4*)(gh + (size_t)e * H))[c4];
    __half2 hh0(__float2half(v.x), __float2half(v.y));
    __half2 hh1(__float2half(v.z), __float2half(v.w));
    ((__half2*)hi)[i * 2 + 0] = hh0;
    ((__half2*)hi)[i * 2 + 1] = hh1;
}

// ============ BK=32 mainloop (proj, 2-term) — R12-proven ======================
#define GEMM_MAINLOOP32(HAS_AL)                                                \
    constexpr uint32_t AH_OFF = 0;                                             \
    constexpr uint32_t AL_OFF = 8192;                                          \
    constexpr uint32_t BH_OFF = (HAS_AL) ? 16384u : 8192u;                     \
    constexpr uint32_t STB = BH_OFF + 16384u;                                  \
    float acc[2][16][4];                                                       \
    _Pragma("unroll") for (int mi = 0; mi < 2; mi++)                           \
    _Pragma("unroll") for (int nj = 0; nj < 16; nj++)                          \
    _Pragma("unroll") for (int q = 0; q < 4; q++) acc[mi][nj][q] = 0.f;        \
    const int nchunks = K / 32;                                                \
    auto load_stage = [&](int s, int k0) {                                     \
        const uint32_t base = sb + s * STB;                                    \
        _Pragma("unroll") for (int i = 0; i < 2; i++) {                        \
            int cid = tid + i * NTH;                                           \
            int row = cid >> 2;                                                \
            int cb = (cid & 3) * 16;                                           \
            int grow = m0 + row;                                               \
            if (grow >= M) grow = M - 1;                                       \
            size_t gb = ((size_t)grow * K + k0) * 2 + cb;                      \
            uint32_t d = base + row * 64 + (cb ^ ((row & 3) << 4));            \
            cp16(d + AH_OFF, (const char*)A + gb);                             \
            if (HAS_AL) cp16(d + AL_OFF, (const char*)AL + gb);                \
        }                                                                      \
        _Pragma("unroll") for (int i = 0; i < 4; i++) {                        \
            int cid = tid + i * NTH;                                           \
            int k = cid >> 5;                                                  \
            int cb = (cid & 31) * 16;                                          \
            size_t gb = (size_t)(k0 + k) * 512 + cb;                           \
            uint32_t d = base + k * 512 + (cb ^ ((k & 7) << 4));               \
            cp16(d + BH_OFF, (const char*)Bz + gb);                            \
        }                                                                      \
        asm volatile("cp.async.commit_group;" ::: "memory");                   \
    };                                                                         \
    auto compute_stage = [&](int s) {                                          \
        const uint32_t base = sb + s * STB;                                    \
        _Pragma("unroll") for (int kk = 0; kk < 2; kk++) {                     \
            uint32_t ah[2][4], al[2][4];                                       \
            _Pragma("unroll") for (int mi = 0; mi < 2; mi++) {                 \
                int row = wm * 32 + mi * 16 + (lane & 15);                     \
                uint32_t cb = kk * 32 + ((lane >> 4) << 4);                    \
                uint32_t ad = base + row * 64 + (cb ^ ((row & 3) << 4));       \
                ldsm4(ah[mi], ad + AH_OFF);                                    \
                if (HAS_AL) ldsm4(al[mi], ad + AL_OFF);                        \
            }                                                                  \
            const int kr = kk * 16 + (lane & 15);                              \
            const uint32_t hi16 = (lane >> 4) << 4;                            \
            uint32_t bhA[4], bhB[4];                                           \
            {                                                                  \
                uint32_t cb = wn * 256 + hi16;                                 \
                uint32_t bd = base + kr * 512 + (cb ^ ((kr & 7) << 4));        \
                ldsm4t(bhA, bd + BH_OFF);                                      \
            }                                                                  \
            _Pragma("unroll") for (int nj2 = 0; nj2 < 8; nj2++) {              \
                uint32_t* ch = (nj2 & 1) ? bhB : bhA;                          \
                if (nj2 < 7) {                                                 \
                    uint32_t* nh = (nj2 & 1) ? bhA : bhB;                      \
                    uint32_t cb = wn * 256 + (nj2 + 1) * 32 + hi16;            \
                    uint32_t bd = base + kr * 512 + (cb ^ ((kr & 7) << 4));    \
                    ldsm4t(nh, bd + BH_OFF);                                   \
                }                                                              \
                _Pragma("unroll") for (int mi = 0; mi < 2; mi++)               \
                _Pragma("unroll") for (int sub = 0; sub < 2; sub++) {          \
                    int nj = nj2 * 2 + sub;                                    \
                    mma16816(acc[mi][nj], ah[mi], &ch[sub * 2]);               \
                    if (HAS_AL) mma16816(acc[mi][nj], al[mi], &ch[sub * 2]);   \
                }                                                              \
            }                                                                  \
        }                                                                      \
    };                                                                         \
    for (int p = 0; p < 3 && p < nchunks; p++) load_stage(p, p * 32);          \
    {                                                                          \
        int cs = 0, ls = 3;                                                    \
        for (int c = 0; c < nchunks; c++) {                                    \
            if (c + 3 < nchunks) load_stage(ls, (c + 3) * 32);                 \
            else asm volatile("cp.async.commit_group;" ::: "memory");          \
            asm volatile("cp.async.wait_group 2;" ::: "memory");               \
            __syncthreads();                                                   \
            compute_stage(cs);                                                 \
            if (++cs == NSTAGE) cs = 0;                                        \
            if (++ls == NSTAGE) ls = 0;                                        \
        }                                                                      \
    }

// ============ BK=128 mainloop (1-term, K=256) — 2 chunks, 2 barriers ==========
// Stage: A 128x256B (SW128) = 32KB at 0, B 128x512B = 64KB at 32KB. 2 stages.
#define GEMM_MAINLOOP128()                                                     \
    constexpr uint32_t BH_OFF = 32768u;                                        \
    constexpr uint32_t STB = 98304u;                                           \
    float acc[2][16][4];                                                       \
    _Pragma("unroll") for (int mi = 0; mi < 2; mi++)                           \
    _Pragma("unroll") for (int nj = 0; nj < 16; nj++)                          \
    _Pragma("unroll") for (int q = 0; q < 4; q++) acc[mi][nj][q] = 0.f;        \
    auto load_stage = [&](int s, int k0) {                                     \
        const uint32_t base = sb + s * STB;                                    \
        _Pragma("unroll") for (int i = 0; i < 8; i++) {                        \
            int cid = tid + i * NTH;                                           \
            int row = cid >> 4;                                                \
            int cb = (cid & 15) * 16;                                          \
            int grow = m0 + row;                                               \
            if (grow >= M) grow = M - 1;                                       \
            size_t gb = ((size_t)grow * K + k0) * 2 + cb;                      \
            uint32_t d = base + row * 256 + (cb ^ ((row & 7) << 4));           \
            cp16(d, (const char*)A + gb);                                      \
        }                                                                      \
        _Pragma("unroll") for (int i = 0; i < 16; i++) {                       \
            int cid = tid + i * NTH;                                           \
            int k = cid >> 5;                                                  \
            int cb = (cid & 31) * 16;                                          \
            size_t gb = (size_t)(k0 + k) * 512 + cb;                           \
            uint32_t d = base + k * 512 + (cb ^ ((k & 7) << 4));               \
            cp16(d + BH_OFF, (const char*)Bz + gb);                            \
        }                                                                      \
        asm volatile("cp.async.commit_group;" ::: "memory");                   \
    };                                                                         \
    auto compute_stage = [&](int s) {                                          \
        const uint32_t base = sb + s * STB;                                    \
        _Pragma("unroll") for (int kk = 0; kk < 8; kk++) {                     \
            uint32_t ah[2][4];                                                 \
            _Pragma("unroll") for (int mi = 0; mi < 2; mi++) {                 \
                int row = wm * 32 + mi * 16 + (lane & 15);                     \
                uint32_t cb = kk * 32 + ((lane >> 4) << 4);                    \
                uint32_t ad = base + row * 256 + (cb ^ ((row & 7) << 4));      \
                ldsm4(ah[mi], ad);                                             \
            }                                                                  \
            const int kr = kk * 16 + (lane & 15);                              \
            const uint32_t hi16 = (lane >> 4) << 4;                            \
            uint32_t bhA[4], bhB[4];                                           \
            {                                                                  \
                uint32_t cb = wn * 256 + hi16;                                 \
                uint32_t bd = base + kr * 512 + (cb ^ ((kr & 7) << 4));        \
                ldsm4t(bhA, bd + BH_OFF);                                      \
            }                                                                  \
            _Pragma("unroll") for (int nj2 = 0; nj2 < 8; nj2++) {              \
                uint32_t* ch = (nj2 & 1) ? bhB : bhA;                          \
                if (nj2 < 7) {                                                 \
                    uint32_t* nh = (nj2 & 1) ? bhA : bhB;                      \
                    uint32_t cb = wn * 256 + (nj2 + 1) * 32 + hi16;            \
                    uint32_t bd = base + kr * 512 + (cb ^ ((kr & 7) << 4));    \
                    ldsm4t(nh, bd + BH_OFF);                                   \
                }                                                              \
                _Pragma("unroll") for (int mi = 0; mi < 2; mi++)               \
                _Pragma("unroll") for (int sub = 0; sub < 2; sub++) {          \
                    int nj = nj2 * 2 + sub;                                    \
                    mma16816(acc[mi][nj], ah[mi], &ch[sub * 2]);               \
                }                                                              \
            }                                                                  \
        }                                                                      \
    };                                                                         \
    load_stage(0, 0);                                                          \
    load_stage(1, 128);                                                        \
    asm volatile("cp.async.wait_group 1;" ::: "memory");                       \
    __syncthreads();                                                           \
    compute_stage(0);                                                          \
    asm volatile("cp.async.wait_group 0;" ::: "memory");                       \
    __syncthreads();                                                           \
    compute_stage(1);

// scalar epilogue (R12)
#define GEMM_EPI_SCALAR(P1, P2, SRC, DST, SBIAS, W2, B2, SOUT)                 \
    {                                                                          \
        float* sred = (float*)smem;                                            \
        __syncthreads();                                                       \
        _Pragma("unroll") for (int mi = 0; mi < 2; mi++)                       \
        _Pragma("unroll") for (int half = 0; half < 2; half++) {               \
            int rowl = wm * 32 + mi * 16 + half * 8 + (lane >> 2);             \
            int row = m0 + rowl;                                               \
            int cl = (row < M) ? row : (M - 1);                                \
            const __half* p1 = (P1) ? ((P1) + (size_t)(SRC)[cl] * 256) : nullptr;\
            const __half* p2 = (P2) ? ((P2) + (size_t)(DST)[cl] * 256) : nullptr;\
            float part = 0.f;                                                  \
            _Pragma("unroll") for (int nj = 0; nj < 16; nj++) {                \
                int col = wn * 128 + nj * 8 + (lane & 3) * 2;                  \
                float2 bv = *(const float2*)((SBIAS) + col);                   \
                float2 wv = *(const float2*)((W2) + col);                      \
                float2 p1v = make_float2(0.f, 0.f), p2v = make_float2(0.f, 0.f);\
                if (p1) p1v = __half22float2(*(const __half2*)(p1 + col));     \
                if (p2) p2v = __half22float2(*(const __half2*)(p2 + col));     \
                float v0 = fmaxf(acc[mi][nj][half * 2 + 0] + bv.x + p1v.x + p2v.x, 0.f);\
                float v1 = fmaxf(acc[mi][nj][half * 2 + 1] + bv.y + p1v.y + p2v.y, 0.f);\
                part = fmaf(v0, wv.x, part);                                   \
                part = fmaf(v1, wv.y, part);                                   \
            }                                                                  \
            part += __shfl_xor_sync(0xffffffffu, part, 1);                     \
            part += __shfl_xor_sync(0xffffffffu, part, 2);                     \
            if ((lane & 3) == 0) sred[rowl * 2 + wn] = part;                   \
        }                                                                      \
        __syncthreads();                                                       \
        if (tid < 128) {                                                       \
            int row = m0 + tid;                                                \
            if (row < M) (SOUT)[row] = sred[tid * 2] + sred[tid * 2 + 1] + (B2)[0];\
        }                                                                      \
    }

// ---------------- input projection GEMM (2-term exact-A, BK=32) ---------------
__global__ void __launch_bounds__(NTH, 1)
proj_gemm(const __half* __restrict__ A, const __half* __restrict__ AL,
          int M, int K, const __half* __restrict__ Bz,
          const float* __restrict__ bias, float* __restrict__ C,
          __half* __restrict__ ohh, __half* __restrict__ ohl)
{
    extern __shared__ char smem[];
    const uint32_t sb = smem_u32(smem);
    const int tid = threadIdx.x;
    const int lane = tid & 31;
    const int wid = tid >> 5;
    const int wm = wid & 3;
    const int wn = wid >> 2;
    const int m0 = blockIdx.x * BM;

    GEMM_MAINLOOP32(true)

#pragma unroll
    for (int mi = 0; mi < 2; mi++) {
#pragma unroll
        for (int half = 0; half < 2; half++) {
            int row = m0 + wm * 32 + mi * 16 + half * 8 + (lane >> 2);
            if (row >= M) continue;
#pragma unroll
            for (int nj = 0; nj < 16; nj++) {
                int col = wn * 128 + nj * 8 + (lane & 3) * 2;
                float2 v;
                v.x = acc[mi][nj][half * 2 + 0] + bias[col];
                v.y = acc[mi][nj][half * 2 + 1] + bias[col + 1];
                *(float2*)(C + (size_t)row * 256 + col) = v;
                __half b0 = __float2half(v.x);
                __half b1 = __float2half(v.y);
                *(__half2*)(ohh + (size_t)row * 256 + col) = __half2(b0, b1);
                *(__half2*)(ohl + (size_t)row * 256 + col) =
                    __half2(__float2half(v.x - __half2float(b0)),
                            __float2half(v.y - __half2float(b1)));
            }
        }
    }
}

// ---------------- node GEMM: P1/P2 (1-term, BK=128, fp16 out) ------------------
__global__ void __launch_bounds__(NTH, 1)
node_gemm(const __half* __restrict__ A, int M, int K,
          const __half* __restrict__ Bh, __half* __restrict__ PC)
{
    extern __shared__ char smem[];
    const uint32_t sb = smem_u32(smem);
    const int tid = threadIdx.x;
    const int lane = tid & 31;
    const int wid = tid >> 5;
    const int wm = wid & 3;
    const int wn = wid >> 2;
    const int m0 = blockIdx.x * BM;
    const int z = blockIdx.z;
    const __half* Bz = Bh + (size_t)z * 65536;

    GEMM_MAINLOOP128()

    __half* Pz = PC + (size_t)z * N_MAX * H;
#pragma unroll
    for (int mi = 0; mi < 2; mi++) {
#pragma unroll
        for (int half = 0; half < 2; half++) {
            int row = m0 + wm * 32 + mi * 16 + half * 8 + (lane >> 2);
            if (row >= M) continue;
#pragma unroll
            for (int nj = 0; nj < 16; nj++) {
                int col = wn * 128 + nj * 8 + (lane & 3) * 2;
                __half2 hp(__float2half(acc[mi][nj][half * 2 + 0]),
                           __float2half(acc[mi][nj][half * 2 + 1]));
                *(__half2*)(Pz + (size_t)row * 256 + col) = hp;
            }
        }
    }
}

// ---------------- edge + eps GEMM (1-term, BK=128, flat 1D grid) ---------------
__global__ void __launch_bounds__(NTH, 1)
edge_eps_gemm(const __half* __restrict__ Aedge, int E,
              const __half* __restrict__ Anode, int Nn, int nblkE,
              const __half* __restrict__ WhL,
              const float* __restrict__ a_b1, const float* __restrict__ a_w2,
              const float* __restrict__ a_b2, float* __restrict__ ae,
              const __half* __restrict__ P1, const __half* __restrict__ P2,
              const float* __restrict__ eps_b1, const float* __restrict__ eps_w2,
              const float* __restrict__ eps_b2, float* __restrict__ epsv)
{
    extern __shared__ char smem[];
    const uint32_t sb = smem_u32(smem);
    const int tid = threadIdx.x;
    const int lane = tid & 31;
    const int wid = tid >> 5;
    const int wm = wid & 3;
    const int wn = wid >> 2;
    const int bid = blockIdx.x;
    const int is_edge = (bid < nblkE);
    const int m0 = (is_edge ? bid : (bid - nblkE)) * BM;
    const int K = H;

    const __half* A = is_edge ? Aedge : Anode;
    const int M = is_edge ? E : Nn;
    const __half* Bz = WhL + (size_t)(is_edge ? 768 : 512) * 256;

    GEMM_MAINLOOP128()

    if (is_edge) {
        GEMM_EPI_SCALAR(P1, P2, g_srcp, g_dstp, a_b1, a_w2, a_b2, ae)
    } else {
        GEMM_EPI_SCALAR((const __half*)nullptr, (const __half*)nullptr,
                        g_srcp, g_dstp, eps_b1, eps_w2, eps_b2, epsv)
    }
}

// ---------------- fused message + softmax + update (R12 version) --------------
__global__ void msg_update(const float* __restrict__ ae,
                           const __half* __restrict__ ghh,
                           const __half* __restrict__ hh_r,
                           const float* __restrict__ h_old,
                           const float* __restrict__ epsv,
                           float* __restrict__ h_new,
                           __half* __restrict__ hh_w, __half* __restrict__ hl_w,
                           int N)
{
    const int w = (blockIdx.x * blockDim.x + threadIdx.x) >> 5;
    const int lane = threadIdx.x & 31;
    if (w >= N) return;
    const int lo = g_off[w], hi = g_off[w + 1];

    float acc8[8];
#pragma unroll
    for (int q = 0; q < 8; q++) acc8[q] = 0.f;
    float s = 0.f;

    if (hi > lo) {
        float mym = -INFINITY;
        for (int j = lo + lane; j < hi; j += 32)
            mym = fmaxf(mym, ae[j]);
#pragma unroll
        for (int o = 16; o; o >>= 1)
            mym = fmaxf(mym, __shfl_xor_sync(0xffffffffu, mym, o));
        const float m = mym;
        for (int base = lo; base < hi; base += 32) {
            const int j = base + lane;
            int sr = 0;
            float c = 0.f;
            if (j < hi) {
                c = __expf(ae[j] - m);
                sr = g_srcp[j];
            }
            s += c;
            const int cnt = min(32, hi - base);
            for (int i = 0; i < cnt; i++) {
                const float ci = __shfl_sync(0xffffffffu, c, i);
                const int si = __shfl_sync(0xffffffffu, sr, i);
                const int ji = base + i;
                const uint4 gv = *(const uint4*)(ghh + (size_t)ji * H + lane * 8);
                const uint4 hv16 = *(const uint4*)(hh_r + (size_t)si * H + lane * 8);
                float2 g0 = __half22float2(*(const __half2*)&gv.x);
                float2 g1 = __half22float2(*(const __half2*)&gv.y);
                float2 g2 = __half22float2(*(const __half2*)&gv.z);
                float2 g3 = __half22float2(*(const __half2*)&gv.w);
                float2 q0 = __half22float2(*(const __half2*)&hv16.x);
                float2 q1 = __half22float2(*(const __half2*)&hv16.y);
                float2 q2 = __half22float2(*(const __half2*)&hv16.z);
                float2 q3 = __half22float2(*(const __half2*)&hv16.w);
                acc8[0] = fmaf(ci * g0.x, q0.x, acc8[0]);
                acc8[1] = fmaf(ci * g0.y, q0.y, acc8[1]);
                acc8[2] = fmaf(ci * g1.x, q1.x, acc8[2]);
                acc8[3] = fmaf(ci * g1.y, q1.y, acc8[3]);
                acc8[4] = fmaf(ci * g2.x, q2.x, acc8[4]);
                acc8[5] = fmaf(ci * g2.y, q2.y, acc8[5]);
                acc8[6] = fmaf(ci * g3.x, q3.x, acc8[6]);
                acc8[7] = fmaf(ci * g3.y, q3.y, acc8[7]);
            }
        }
#pragma unroll
        for (int o = 16; o; o >>= 1)
            s += __shfl_xor_sync(0xffffffffu, s, o);
    }

    const float inv = (s > 0.f) ? (1.f / s) : 0.f;
    const float scale = (1.f + epsv[w]) * inv;

    const float4* hrow = (const float4*)(h_old + (size_t)w * H + lane * 8);
    float4 o0 = hrow[0], o1 = hrow[1];
    float4 r0, r1;
    r0.x = fmaf(acc8[0], scale, o0.x); r0.y = fmaf(acc8[1], scale, o0.y);
    r0.z = fmaf(acc8[2], scale, o0.z); r0.w = fmaf(acc8[3], scale, o0.w);
    r1.x = fmaf(acc8[4], scale, o1.x); r1.y = fmaf(acc8[5], scale, o1.y);
    r1.z = fmaf(acc8[6], scale, o1.z); r1.w = fmaf(acc8[7], scale, o1.w);
    float4* orow = (float4*)(h_new + (size_t)w * H + lane * 8);
    orow[0] = r0;
    orow[1] = r1;

    __half2 hp[4], lp[4];
    float vv[8] = {r0.x, r0.y, r0.z, r0.w, r1.x, r1.y, r1.z, r1.w};
#pragma unroll
    for (int q = 0; q < 4; q++) {
        __half b0 = __float2half(vv[q * 2]);
        __half b1 = __float2half(vv[q * 2 + 1]);
        hp[q] = __half2(b0, b1);
        lp[q] = __half2(__float2half(vv[q * 2] - __half2float(b0)),
                        __float2half(vv[q * 2 + 1] - __half2float(b1)));
    }
    *(uint4*)(hh_w + (size_t)w * H + lane * 8) = *(uint4*)hp;
    *(uint4*)(hl_w + (size_t)w * H + lane * 8) = *(uint4*)lp;
}

// ---------------- launch -------------------------------------------------------
extern "C" void kernel_launch(void* const* d_in, const int* in_sizes, int n_in,
                              void* d_out, int out_size)
{
    (void)n_in; (void)out_size;
    const float* node_feats = (const float*)d_in[0];
    const float* gh         = (const float*)d_in[1];
    const int*   src        = (const int*)d_in[2];
    const int*   dst        = (const int*)d_in[3];
    const float* Wn_w       = (const float*)d_in[4];
    const float* Wn_b       = (const float*)d_in[5];
    const float* eps_w1     = (const float*)d_in[6];
    const float* eps_b1     = (const float*)d_in[7];
    const float* eps_w2     = (const float*)d_in[8];
    const float* eps_b2     = (const float*)d_in[9];
    const float* a_w1       = (const float*)d_in[10];
    const float* a_b1       = (const float*)d_in[11];
    const float* a_w2       = (const float*)d_in[12];
    const float* a_b2       = (const float*)d_in[13];

    const int D_IN = 128;
    const int N = in_sizes[0] / D_IN;
    const int E = in_sizes[2];
    const int L = in_sizes[6] / (H * H);

    float* out = (float*)d_out;

    __half *ghh, *nfh, *nfl, *hh0, *hl0, *Wh, *wnh, *gP;
    float *epsv, *ae;
    cudaGetSymbolAddress((void**)&ghh, g_ghh);
    cudaGetSymbolAddress((void**)&nfh, g_nfh);
    cudaGetSymbolAddress((void**)&nfl, g_nfl);
    cudaGetSymbolAddress((void**)&hh0, g_hh);
    cudaGetSymbolAddress((void**)&hl0, g_hl);
    cudaGetSymbolAddress((void**)&Wh,  g_Wh);
    cudaGetSymbolAddress((void**)&wnh, g_wnh);
    cudaGetSymbolAddress((void**)&gP,   g_P);
    cudaGetSymbolAddress((void**)&epsv, g_eps);
    cudaGetSymbolAddress((void**)&ae,   g_ae);

    constexpr int SMEM2 = NSTAGE * (16384 + 16384);   // proj (BK=32, 2-term) = 160KB
    constexpr int SMEM128 = 2 * 98304;                // 1-term BK=128 = 192KB
    cudaFuncSetAttribute(proj_gemm, cudaFuncAttributeMaxDynamicSharedMemorySize, SMEM2);
    cudaFuncSetAttribute(node_gemm, cudaFuncAttributeMaxDynamicSharedMemorySize, SMEM128);
    cudaFuncSetAttribute(edge_eps_gemm, cudaFuncAttributeMaxDynamicSharedMemorySize, SMEM128);

    // one-time prep
    {
        int totw = L * 1024 * 256 + 128 * 256;
        prep_w<<<(totw + 255) / 256, 256>>>(a_w1, eps_w1, Wn_w, L, N);
        int n4 = (N * D_IN) / 4;
        int thr = (n4 > E) ? n4 : E;
        cvt_nf_hist<<<(thr + 255) / 256, 256>>>(node_feats, nfh, nfl, n4, dst, E);
        csr_scan<<<1, 1024>>>(N, E);
        csr_scatter<<<(E + 255) / 256, 256>>>(src, dst, E);
        int g4 = (E * H) / 4;
        cvt_gh_perm<<<(g4 + 255) / 256, 256>>>(gh, ghh, g4);
    }

    const int nblkN = (N + BM - 1) / BM;
    const int nblkE = (E + BM - 1) / BM;
    const size_t hbuf = (size_t)N_MAX * H;

    proj_gemm<<<dim3(nblkN, 1, 1), NTH, SMEM2>>>(
        nfh, nfl, N, D_IN, wnh, Wn_b, out, hh0, hl0);

    for (int l = 0; l < L; l++) {
        const float* hcur = out + (size_t)l * N * H;
        float*       hnext = out + (size_t)(l + 1) * N * H;
        const __half* WhL = Wh + (size_t)l * 1024 * 256;
        __half* hhr = hh0 + (size_t)(l & 1) * hbuf;
        __half* hhw = hh0 + (size_t)((l + 1) & 1) * hbuf;
        __half* hlw = hl0 + (size_t)((l + 1) & 1) * hbuf;

        node_gemm<<<dim3(nblkN, 1, 2), NTH, SMEM128>>>(hhr, N, H, WhL, gP);

        edge_eps_gemm<<<dim3(nblkE + nblkN, 1, 1), NTH, SMEM128>>>(
            ghh, E, hhr, N, nblkE, WhL,
            a_b1 + (size_t)l * H, a_w2 + (size_t)l * H, a_b2 + l, ae,
            gP, gP + hbuf,
            eps_b1 + (size_t)l * H, eps_w2 + (size_t)l * H, eps_b2 + l, epsv);

        msg_update<<<(N * 32 + 255) / 256, 256>>>(
            ae, ghh, hhr, hcur, epsv, hnext, hhw, hlw, N);
    }
}

// round 17
// speedup vs baseline: 1.1267x; 1.0351x over previous
#include <cuda_runtime.h>
#include <cuda_fp16.h>
#include <math.h>
#include <stdint.h>

#define H 256
#define N_MAX 10240
#define E_MAX 163840
#define L_MAX 3

#define BM 128
#define BN 256
#define NTH 256
#define NSTAGE 5     // BK=32 path (proj)

// ---------------- scratch (device globals) ---------------------------------
__device__ __half g_ghh[E_MAX * H];            // gh fp16, PERMUTED by dst-sorted order
__device__ __half g_nfh[N_MAX * 128];
__device__ __half g_nfl[N_MAX * 128];
__device__ __half g_hh[2][N_MAX * H];
__device__ __half g_hl[2][N_MAX * H];
__device__ __half g_Wh[L_MAX * 1024 * 256];
__device__ __half g_wnh[128 * 256];
__device__ __half g_P[2 * N_MAX * H];
__device__ float g_eps[N_MAX];
__device__ float g_ae[E_MAX];
__device__ int g_cnt[N_MAX];
__device__ int g_off[N_MAX + 1];
__device__ int g_cur[N_MAX];
__device__ int g_perm[E_MAX];
__device__ int g_srcp[E_MAX];
__device__ int g_dstp[E_MAX];

// ---------------- helpers ----------------------------------------------------
__device__ __forceinline__ uint32_t smem_u32(const void* p) {
    uint32_t a;
    asm("{ .reg .u64 t; cvta.to.shared.u64 t, %1; cvt.u32.u64 %0, t; }" : "=r"(a) : "l"(p));
    return a;
}
__device__ __forceinline__ void cp16(uint32_t dst, const void* src) {
    asm volatile("cp.async.cg.shared.global [%0], [%1], 16;" :: "r"(dst), "l"(src));
}
__device__ __forceinline__ void ldsm4(uint32_t* r, uint32_t addr) {
    asm volatile("ldmatrix.sync.aligned.m8n8.x4.shared.b16 {%0,%1,%2,%3}, [%4];"
                 : "=r"(r[0]), "=r"(r[1]), "=r"(r[2]), "=r"(r[3]) : "r"(addr));
}
__device__ __forceinline__ void ldsm4t(uint32_t* r, uint32_t addr) {
    asm volatile("ldmatrix.sync.aligned.m8n8.x4.trans.shared.b16 {%0,%1,%2,%3}, [%4];"
                 : "=r"(r[0]), "=r"(r[1]), "=r"(r[2]), "=r"(r[3]) : "r"(addr));
}
__device__ __forceinline__ void mma16816(float* c, const uint32_t* a, const uint32_t* b) {
    asm volatile("mma.sync.aligned.m16n8k16.row.col.f32.f16.f16.f32 "
                 "{%0,%1,%2,%3}, {%4,%5,%6,%7}, {%8,%9}, {%0,%1,%2,%3};"
                 : "+f"(c[0]), "+f"(c[1]), "+f"(c[2]), "+f"(c[3])
                 : "r"(a[0]), "r"(a[1]), "r"(a[2]), "r"(a[3]), "r"(b[0]), "r"(b[1]));
}

// ---------------- weight prep (hi only) + csr clear ---------------------------
__global__ void prep_w(const float* __restrict__ a_w1, const float* __restrict__ eps_w1,
                       const float* __restrict__ Wn_w, int L, int N)
{
    const int totW = L * 1024 * 256;
    const int total = totW + 128 * 256;
    int idx = blockIdx.x * blockDim.x + threadIdx.x;
    if (idx < N) g_cnt[idx] = 0;
    if (idx >= total) return;
    float v;
    __half* dh;
    int di;
    if (idx < totW) {
        int l = idx / (1024 * 256);
        int r = (idx / 256) % 1024;
        int n = idx % 256;
        if (r < 512)      v = a_w1[((size_t)l * 768 + r) * 256 + n];
        else if (r < 768) v = eps_w1[((size_t)l * 256 + (r - 512)) * 256 + n];
        else              v = a_w1[((size_t)l * 768 + 512 + (r - 768)) * 256 + n];
        dh = g_Wh; di = idx;
    } else {
        int i2 = idx - totW;
        v = Wn_w[i2];
        dh = g_wnh; di = i2;
    }
    dh[di] = __float2half(v);
}

// ---------------- nf cvt (fp16 hi/lo) + csr_hist fused ------------------------
__global__ void cvt_nf_hist(const float* __restrict__ x, __half* __restrict__ hi,
                            __half* __restrict__ lo, int n4,
                            const int* __restrict__ dst, int E)
{
    int i = blockIdx.x * blockDim.x + threadIdx.x;
    if (i < E) atomicAdd(&g_cnt[dst[i]], 1);
    if (i >= n4) return;
    float4 v = ((const float4*)x)[i];
    __half h0 = __float2half(v.x), h1 = __float2half(v.y);
    __half h2 = __float2half(v.z), h3 = __float2half(v.w);
    ((__half2*)hi)[i * 2 + 0] = __half2(h0, h1);
    ((__half2*)hi)[i * 2 + 1] = __half2(h2, h3);
    ((__half2*)lo)[i * 2 + 0] = __half2(__float2half(v.x - __half2float(h0)),
                                        __float2half(v.y - __half2float(h1)));
    ((__half2*)lo)[i * 2 + 1] = __half2(__float2half(v.z - __half2float(h2)),
                                        __float2half(v.w - __half2float(h3)));
}

// ---------------- CSR scan (warp-shuffle two-level) ----------------------------
__global__ void csr_scan(int N, int E) {
    __shared__ int wsum[32];
    const int tid = threadIdx.x;
    const int lane = tid & 31;
    const int wrp = tid >> 5;
    const int chunk = (N + 1023) / 1024;
    const int base = tid * chunk;
    int s = 0;
#pragma unroll 4
    for (int i = 0; i < chunk; i++) {
        int idx = base + i;
        if (idx < N) s += g_cnt[idx];
    }
    int sc = s;
#pragma unroll
    for (int o = 1; o < 32; o <<= 1) {
        int v = __shfl_up_sync(0xffffffffu, sc, o);
        if (lane >= o) sc += v;
    }
    if (lane == 31) wsum[wrp] = sc;
    __syncthreads();
    if (wrp == 0) {
        int t = wsum[lane];
#pragma unroll
        for (int o = 1; o < 32; o <<= 1) {
            int v = __shfl_up_sync(0xffffffffu, t, o);
            if (lane >= o) t += v;
        }
        wsum[lane] = t;
    }
    __syncthreads();
    int run = sc - s + (wrp ? wsum[wrp - 1] : 0);
    for (int i = 0; i < chunk; i++) {
        int idx = base + i;
        if (idx < N) { g_off[idx] = run; g_cur[idx] = run; run += g_cnt[idx]; }
    }
    if (tid == 1023) g_off[N] = E;
}

__global__ void csr_scatter(const int* __restrict__ src, const int* __restrict__ dst,
                            int E)
{
    int e = blockIdx.x * blockDim.x + threadIdx.x;
    if (e < E) {
        int d = dst[e];
        int pos = atomicAdd(&g_cur[d], 1);
        g_perm[pos] = e;
        g_srcp[pos] = src[e];
        g_dstp[pos] = d;
    }
}

__global__ void cvt_gh_perm(const float* __restrict__ gh, __half* __restrict__ hi,
                            int n4)
{
    int i = blockIdx.x * blockDim.x + threadIdx.x;
    if (i >= n4) return;
    const int row = i >> 6;
    const int c4 = i & 63;
    const int e = g_perm[row];
    float4 v = ((const float4*)(gh + (size_t)e * H))[c4];
    __half2 hh0(__float2half(v.x), __float2half(v.y));
    __half2 hh1(__float2half(v.z), __float2half(v.w));
    ((__half2*)hi)[i * 2 + 0] = hh0;
    ((__half2*)hi)[i * 2 + 1] = hh1;
}

// ============ BK=32 mainloop (proj, 2-term) — R12-proven ======================
#define GEMM_MAINLOOP32(HAS_AL)                                                \
    constexpr uint32_t AH_OFF = 0;                                             \
    constexpr uint32_t AL_OFF = 8192;                                          \
    constexpr uint32_t BH_OFF = (HAS_AL) ? 16384u : 8192u;                     \
    constexpr uint32_t STB = BH_OFF + 16384u;                                  \
    float acc[2][16][4];                                                       \
    _Pragma("unroll") for (int mi = 0; mi < 2; mi++)                           \
    _Pragma("unroll") for (int nj = 0; nj < 16; nj++)                          \
    _Pragma("unroll") for (int q = 0; q < 4; q++) acc[mi][nj][q] = 0.f;        \
    const int nchunks = K / 32;                                                \
    auto load_stage = [&](int s, int k0) {                                     \
        const uint32_t base = sb + s * STB;                                    \
        _Pragma("unroll") for (int i = 0; i < 2; i++) {                        \
            int cid = tid + i * NTH;                                           \
            int row = cid >> 2;                                                \
            int cb = (cid & 3) * 16;                                           \
            int grow = m0 + row;                                               \
            if (grow >= M) grow = M - 1;                                       \
            size_t gb = ((size_t)grow * K + k0) * 2 + cb;                      \
            uint32_t d = base + row * 64 + (cb ^ ((row & 3) << 4));            \
            cp16(d + AH_OFF, (const char*)A + gb);                             \
            if (HAS_AL) cp16(d + AL_OFF, (const char*)AL + gb);                \
        }                                                                      \
        _Pragma("unroll") for (int i = 0; i < 4; i++) {                        \
            int cid = tid + i * NTH;                                           \
            int k = cid >> 5;                                                  \
            int cb = (cid & 31) * 16;                                          \
            size_t gb = (size_t)(k0 + k) * 512 + cb;                           \
            uint32_t d = base + k * 512 + (cb ^ ((k & 7) << 4));               \
            cp16(d + BH_OFF, (const char*)Bz + gb);                            \
        }                                                                      \
        asm volatile("cp.async.commit_group;" ::: "memory");                   \
    };                                                                         \
    auto compute_stage = [&](int s) {                                          \
        const uint32_t base = sb + s * STB;                                    \
        _Pragma("unroll") for (int kk = 0; kk < 2; kk++) {                     \
            uint32_t ah[2][4], al[2][4];                                       \
            _Pragma("unroll") for (int mi = 0; mi < 2; mi++) {                 \
                int row = wm * 32 + mi * 16 + (lane & 15);                     \
                uint32_t cb = kk * 32 + ((lane >> 4) << 4);                    \
                uint32_t ad = base + row * 64 + (cb ^ ((row & 3) << 4));       \
                ldsm4(ah[mi], ad + AH_OFF);                                    \
                if (HAS_AL) ldsm4(al[mi], ad + AL_OFF);                        \
            }                                                                  \
            const int kr = kk * 16 + (lane & 15);                              \
            const uint32_t hi16 = (lane >> 4) << 4;                            \
            uint32_t bhA[4], bhB[4];                                           \
            {                                                                  \
                uint32_t cb = wn * 256 + hi16;                                 \
                uint32_t bd = base + kr * 512 + (cb ^ ((kr & 7) << 4));        \
                ldsm4t(bhA, bd + BH_OFF);                                      \
            }                                                                  \
            _Pragma("unroll") for (int nj2 = 0; nj2 < 8; nj2++) {              \
                uint32_t* ch = (nj2 & 1) ? bhB : bhA;                          \
                if (nj2 < 7) {                                                 \
                    uint32_t* nh = (nj2 & 1) ? bhA : bhB;                      \
                    uint32_t cb = wn * 256 + (nj2 + 1) * 32 + hi16;            \
                    uint32_t bd = base + kr * 512 + (cb ^ ((kr & 7) << 4));    \
                    ldsm4t(nh, bd + BH_OFF);                                   \
                }                                                              \
                _Pragma("unroll") for (int mi = 0; mi < 2; mi++)               \
                _Pragma("unroll") for (int sub = 0; sub < 2; sub++) {          \
                    int nj = nj2 * 2 + sub;                                    \
                    mma16816(acc[mi][nj], ah[mi], &ch[sub * 2]);               \
                    if (HAS_AL) mma16816(acc[mi][nj], al[mi], &ch[sub * 2]);   \
                }                                                              \
            }                                                                  \
        }                                                                      \
    };                                                                         \
    for (int p = 0; p < 3 && p < nchunks; p++) load_stage(p, p * 32);          \
    {                                                                          \
        int cs = 0, ls = 3;                                                    \
        for (int c = 0; c < nchunks; c++) {                                    \
            if (c + 3 < nchunks) load_stage(ls, (c + 3) * 32);                 \
            else asm volatile("cp.async.commit_group;" ::: "memory");          \
            asm volatile("cp.async.wait_group 2;" ::: "memory");               \
            __syncthreads();                                                   \
            compute_stage(cs);                                                 \
            if (++cs == NSTAGE) cs = 0;                                        \
            if (++ls == NSTAGE) ls = 0;                                        \
        }                                                                      \
    }

// ============ BK=128 mainloop (1-term, K=256) — 2 chunks, 2 barriers ==========
#define GEMM_MAINLOOP128()                                                     \
    constexpr uint32_t BH_OFF = 32768u;                                        \
    constexpr uint32_t STB = 98304u;                                           \
    float acc[2][16][4];                                                       \
    _Pragma("unroll") for (int mi = 0; mi < 2; mi++)                           \
    _Pragma("unroll") for (int nj = 0; nj < 16; nj++)                          \
    _Pragma("unroll") for (int q = 0; q < 4; q++) acc[mi][nj][q] = 0.f;        \
    auto load_stage = [&](int s, int k0) {                                     \
        const uint32_t base = sb + s * STB;                                    \
        _Pragma("unroll") for (int i = 0; i < 8; i++) {                        \
            int cid = tid + i * NTH;                                           \
            int row = cid >> 4;                                                \
            int cb = (cid & 15) * 16;                                          \
            int grow = m0 + row;                                               \
            if (grow >= M) grow = M - 1;                                       \
            size_t gb = ((size_t)grow * K + k0) * 2 + cb;                      \
            uint32_t d = base + row * 256 + (cb ^ ((row & 7) << 4));           \
            cp16(d, (const char*)A + gb);                                      \
        }                                                                      \
        _Pragma("unroll") for (int i = 0; i < 16; i++) {                       \
            int cid = tid + i * NTH;                                           \
            int k = cid >> 5;                                                  \
            int cb = (cid & 31) * 16;                                          \
            size_t gb = (size_t)(k0 + k) * 512 + cb;                           \
            uint32_t d = base + k * 512 + (cb ^ ((k & 7) << 4));               \
            cp16(d + BH_OFF, (const char*)Bz + gb);                            \
        }                                                                      \
        asm volatile("cp.async.commit_group;" ::: "memory");                   \
    };                                                                         \
    auto compute_stage = [&](int s) {                                          \
        const uint32_t base = sb + s * STB;                                    \
        _Pragma("unroll") for (int kk = 0; kk < 8; kk++) {                     \
            uint32_t ah[2][4];                                                 \
            _Pragma("unroll") for (int mi = 0; mi < 2; mi++) {                 \
                int row = wm * 32 + mi * 16 + (lane & 15);                     \
                uint32_t cb = kk * 32 + ((lane >> 4) << 4);                    \
                uint32_t ad = base + row * 256 + (cb ^ ((row & 7) << 4));      \
                ldsm4(ah[mi], ad);                                             \
            }                                                                  \
            const int kr = kk * 16 + (lane & 15);                              \
            const uint32_t hi16 = (lane >> 4) << 4;                            \
            uint32_t bhA[4], bhB[4];                                           \
            {                                                                  \
                uint32_t cb = wn * 256 + hi16;                                 \
                uint32_t bd = base + kr * 512 + (cb ^ ((kr & 7) << 4));        \
                ldsm4t(bhA, bd + BH_OFF);                                      \
            }                                                                  \
            _Pragma("unroll") for (int nj2 = 0; nj2 < 8; nj2++) {              \
                uint32_t* ch = (nj2 & 1) ? bhB : bhA;                          \
                if (nj2 < 7) {                                                 \
                    uint32_t* nh = (nj2 & 1) ? bhA : bhB;                      \
                    uint32_t cb = wn * 256 + (nj2 + 1) * 32 + hi16;            \
                    uint32_t bd = base + kr * 512 + (cb ^ ((kr & 7) << 4));    \
                    ldsm4t(nh, bd + BH_OFF);                                   \
                }                                                              \
                _Pragma("unroll") for (int mi = 0; mi < 2; mi++)               \
                _Pragma("unroll") for (int sub = 0; sub < 2; sub++) {          \
                    int nj = nj2 * 2 + sub;                                    \
                    mma16816(acc[mi][nj], ah[mi], &ch[sub * 2]);               \
                }                                                              \
            }                                                                  \
        }                                                                      \
    };                                                                         \
    load_stage(0, 0);                                                          \
    load_stage(1, 128);                                                        \
    asm volatile("cp.async.wait_group 1;" ::: "memory");                       \
    __syncthreads();                                                           \
    compute_stage(0);                                                          \
    asm volatile("cp.async.wait_group 0;" ::: "memory");                       \
    __syncthreads();                                                           \
    compute_stage(1);

// scalar epilogue
#define GEMM_EPI_SCALAR(P1, P2, SRC, DST, SBIAS, W2, B2, SOUT)                 \
    {                                                                          \
        float* sred = (float*)smem;                                            \
        __syncthreads();                                                       \
        _Pragma("unroll") for (int mi = 0; mi < 2; mi++)                       \
        _Pragma("unroll") for (int half = 0; half < 2; half++) {               \
            int rowl = wm * 32 + mi * 16 + half * 8 + (lane >> 2);             \
            int row = m0 + rowl;                                               \
            int cl = (row < M) ? row : (M - 1);                                \
            const __half* p1 = (P1) ? ((P1) + (size_t)(SRC)[cl] * 256) : nullptr;\
            const __half* p2 = (P2) ? ((P2) + (size_t)(DST)[cl] * 256) : nullptr;\
            float part = 0.f;                                                  \
            _Pragma("unroll") for (int nj = 0; nj < 16; nj++) {                \
                int col = wn * 128 + nj * 8 + (lane & 3) * 2;                  \
                float2 bv = *(const float2*)((SBIAS) + col);                   \
                float2 wv = *(const float2*)((W2) + col);                      \
                float2 p1v = make_float2(0.f, 0.f), p2v = make_float2(0.f, 0.f);\
                if (p1) p1v = __half22float2(*(const __half2*)(p1 + col));     \
                if (p2) p2v = __half22float2(*(const __half2*)(p2 + col));     \
                float v0 = fmaxf(acc[mi][nj][half * 2 + 0] + bv.x + p1v.x + p2v.x, 0.f);\
                float v1 = fmaxf(acc[mi][nj][half * 2 + 1] + bv.y + p1v.y + p2v.y, 0.f);\
                part = fmaf(v0, wv.x, part);                                   \
                part = fmaf(v1, wv.y, part);                                   \
            }                                                                  \
            part += __shfl_xor_sync(0xffffffffu, part, 1);                     \
            part += __shfl_xor_sync(0xffffffffu, part, 2);                     \
            if ((lane & 3) == 0) sred[rowl * 2 + wn] = part;                   \
        }                                                                      \
        __syncthreads();                                                       \
        if (tid < 128) {                                                       \
            int row = m0 + tid;                                                \
            if (row < M) (SOUT)[row] = sred[tid * 2] + sred[tid * 2 + 1] + (B2)[0];\
        }                                                                      \
    }

// ---------------- input projection GEMM (2-term exact-A, BK=32) ---------------
__global__ void __launch_bounds__(NTH, 1)
proj_gemm(const __half* __restrict__ A, const __half* __restrict__ AL,
          int M, int K, const __half* __restrict__ Bz,
          const float* __restrict__ bias, float* __restrict__ C,
          __half* __restrict__ ohh, __half* __restrict__ ohl)
{
    extern __shared__ char smem[];
    const uint32_t sb = smem_u32(smem);
    const int tid = threadIdx.x;
    const int lane = tid & 31;
    const int wid = tid >> 5;
    const int wm = wid & 3;
    const int wn = wid >> 2;
    const int m0 = blockIdx.x * BM;

    GEMM_MAINLOOP32(true)

#pragma unroll
    for (int mi = 0; mi < 2; mi++) {
#pragma unroll
        for (int half = 0; half < 2; half++) {
            int row = m0 + wm * 32 + mi * 16 + half * 8 + (lane >> 2);
            if (row >= M) continue;
#pragma unroll
            for (int nj = 0; nj < 16; nj++) {
                int col = wn * 128 + nj * 8 + (lane & 3) * 2;
                float2 v;
                v.x = acc[mi][nj][half * 2 + 0] + bias[col];
                v.y = acc[mi][nj][half * 2 + 1] + bias[col + 1];
                *(float2*)(C + (size_t)row * 256 + col) = v;
                __half b0 = __float2half(v.x);
                __half b1 = __float2half(v.y);
                *(__half2*)(ohh + (size_t)row * 256 + col) = __half2(b0, b1);
                *(__half2*)(ohl + (size_t)row * 256 + col) =
                    __half2(__float2half(v.x - __half2float(b0)),
                            __float2half(v.y - __half2float(b1)));
            }
        }
    }
}

// ---------------- node GEMM: P1/P2 (1-term, BK=128, fp16 out) ------------------
__global__ void __launch_bounds__(NTH, 1)
node_gemm(const __half* __restrict__ A, int M, int K,
          const __half* __restrict__ Bh, __half* __restrict__ PC)
{
    extern __shared__ char smem[];
    const uint32_t sb = smem_u32(smem);
    const int tid = threadIdx.x;
    const int lane = tid & 31;
    const int wid = tid >> 5;
    const int wm = wid & 3;
    const int wn = wid >> 2;
    const int m0 = blockIdx.x * BM;
    const int z = blockIdx.z;
    const __half* Bz = Bh + (size_t)z * 65536;

    GEMM_MAINLOOP128()

    __half* Pz = PC + (size_t)z * N_MAX * H;
#pragma unroll
    for (int mi = 0; mi < 2; mi++) {
#pragma unroll
        for (int half = 0; half < 2; half++) {
            int row = m0 + wm * 32 + mi * 16 + half * 8 + (lane >> 2);
            if (row >= M) continue;
#pragma unroll
            for (int nj = 0; nj < 16; nj++) {
                int col = wn * 128 + nj * 8 + (lane & 3) * 2;
                __half2 hp(__float2half(acc[mi][nj][half * 2 + 0]),
                           __float2half(acc[mi][nj][half * 2 + 1]));
                *(__half2*)(Pz + (size_t)row * 256 + col) = hp;
            }
        }
    }
}

// ---------------- edge + eps GEMM (1-term, BK=128, flat 1D grid) ---------------
__global__ void __launch_bounds__(NTH, 1)
edge_eps_gemm(const __half* __restrict__ Aedge, int E,
              const __half* __restrict__ Anode, int Nn, int nblkE,
              const __half* __restrict__ WhL,
              const float* __restrict__ a_b1, const float* __restrict__ a_w2,
              const float* __restrict__ a_b2, float* __restrict__ ae,
              const __half* __restrict__ P1, const __half* __restrict__ P2,
              const float* __restrict__ eps_b1, const float* __restrict__ eps_w2,
              const float* __restrict__ eps_b2, float* __restrict__ epsv)
{
    extern __shared__ char smem[];
    const uint32_t sb = smem_u32(smem);
    const int tid = threadIdx.x;
    const int lane = tid & 31;
    const int wid = tid >> 5;
    const int wm = wid & 3;
    const int wn = wid >> 2;
    const int bid = blockIdx.x;
    const int is_edge = (bid < nblkE);
    const int m0 = (is_edge ? bid : (bid - nblkE)) * BM;
    const int K = H;

    const __half* A = is_edge ? Aedge : Anode;
    const int M = is_edge ? E : Nn;
    const __half* Bz = WhL + (size_t)(is_edge ? 768 : 512) * 256;

    GEMM_MAINLOOP128()

    if (is_edge) {
        GEMM_EPI_SCALAR(P1, P2, g_srcp, g_dstp, a_b1, a_w2, a_b2, ae)
    } else {
        GEMM_EPI_SCALAR((const __half*)nullptr, (const __half*)nullptr,
                        g_srcp, g_dstp, eps_b1, eps_w2, eps_b2, epsv)
    }
}

// ---------------- fused message + softmax + update (R12 version) --------------
__global__ void msg_update(const float* __restrict__ ae,
                           const __half* __restrict__ ghh,
                           const __half* __restrict__ hh_r,
                           const float* __restrict__ h_old,
                           const float* __restrict__ epsv,
                           float* __restrict__ h_new,
                           __half* __restrict__ hh_w, __half* __restrict__ hl_w,
                           int N)
{
    const int w = (blockIdx.x * blockDim.x + threadIdx.x) >> 5;
    const int lane = threadIdx.x & 31;
    if (w >= N) return;
    const int lo = g_off[w], hi = g_off[w + 1];

    float acc8[8];
#pragma unroll
    for (int q = 0; q < 8; q++) acc8[q] = 0.f;
    float s = 0.f;

    if (hi > lo) {
        float mym = -INFINITY;
        for (int j = lo + lane; j < hi; j += 32)
            mym = fmaxf(mym, ae[j]);
#pragma unroll
        for (int o = 16; o; o >>= 1)
            mym = fmaxf(mym, __shfl_xor_sync(0xffffffffu, mym, o));
        const float m = mym;
        for (int base = lo; base < hi; base += 32) {
            const int j = base + lane;
            int sr = 0;
            float c = 0.f;
            if (j < hi) {
                c = __expf(ae[j] - m);
                sr = g_srcp[j];
            }
            s += c;
            const int cnt = min(32, hi - base);
            for (int i = 0; i < cnt; i++) {
                const float ci = __shfl_sync(0xffffffffu, c, i);
                const int si = __shfl_sync(0xffffffffu, sr, i);
                const int ji = base + i;
                const uint4 gv = *(const uint4*)(ghh + (size_t)ji * H + lane * 8);
                const uint4 hv16 = *(const uint4*)(hh_r + (size_t)si * H + lane * 8);
                float2 g0 = __half22float2(*(const __half2*)&gv.x);
                float2 g1 = __half22float2(*(const __half2*)&gv.y);
                float2 g2 = __half22float2(*(const __half2*)&gv.z);
                float2 g3 = __half22float2(*(const __half2*)&gv.w);
                float2 q0 = __half22float2(*(const __half2*)&hv16.x);
                float2 q1 = __half22float2(*(const __half2*)&hv16.y);
                float2 q2 = __half22float2(*(const __half2*)&hv16.z);
                float2 q3 = __half22float2(*(const __half2*)&hv16.w);
                acc8[0] = fmaf(ci * g0.x, q0.x, acc8[0]);
                acc8[1] = fmaf(ci * g0.y, q0.y, acc8[1]);
                acc8[2] = fmaf(ci * g1.x, q1.x, acc8[2]);
                acc8[3] = fmaf(ci * g1.y, q1.y, acc8[3]);
                acc8[4] = fmaf(ci * g2.x, q2.x, acc8[4]);
                acc8[5] = fmaf(ci * g2.y, q2.y, acc8[5]);
                acc8[6] = fmaf(ci * g3.x, q3.x, acc8[6]);
                acc8[7] = fmaf(ci * g3.y, q3.y, acc8[7]);
            }
        }
#pragma unroll
        for (int o = 16; o; o >>= 1)
            s += __shfl_xor_sync(0xffffffffu, s, o);
    }

    const float inv = (s > 0.f) ? (1.f / s) : 0.f;
    const float scale = (1.f + epsv[w]) * inv;

    const float4* hrow = (const float4*)(h_old + (size_t)w * H + lane * 8);
    float4 o0 = hrow[0], o1 = hrow[1];
    float4 r0, r1;
    r0.x = fmaf(acc8[0], scale, o0.x); r0.y = fmaf(acc8[1], scale, o0.y);
    r0.z = fmaf(acc8[2], scale, o0.z); r0.w = fmaf(acc8[3], scale, o0.w);
    r1.x = fmaf(acc8[4], scale, o1.x); r1.y = fmaf(acc8[5], scale, o1.y);
    r1.z = fmaf(acc8[6], scale, o1.z); r1.w = fmaf(acc8[7], scale, o1.w);
    float4* orow = (float4*)(h_new + (size_t)w * H + lane * 8);
    orow[0] = r0;
    orow[1] = r1;

    __half2 hp[4], lp[4];
    float vv[8] = {r0.x, r0.y, r0.z, r0.w, r1.x, r1.y, r1.z, r1.w};
#pragma unroll
    for (int q = 0; q < 4; q++) {
        __half b0 = __float2half(vv[q * 2]);
        __half b1 = __float2half(vv[q * 2 + 1]);
        hp[q] = __half2(b0, b1);
        lp[q] = __half2(__float2half(vv[q * 2] - __half2float(b0)),
                        __float2half(vv[q * 2 + 1] - __half2float(b1)));
    }
    *(uint4*)(hh_w + (size_t)w * H + lane * 8) = *(uint4*)hp;
    *(uint4*)(hl_w + (size_t)w * H + lane * 8) = *(uint4*)lp;
}

// ---------------- launch -------------------------------------------------------
extern "C" void kernel_launch(void* const* d_in, const int* in_sizes, int n_in,
                              void* d_out, int out_size)
{
    (void)n_in; (void)out_size;
    const float* node_feats = (const float*)d_in[0];
    const float* gh         = (const float*)d_in[1];
    const int*   src        = (const int*)d_in[2];
    const int*   dst        = (const int*)d_in[3];
    const float* Wn_w       = (const float*)d_in[4];
    const float* Wn_b       = (const float*)d_in[5];
    const float* eps_w1     = (const float*)d_in[6];
    const float* eps_b1     = (const float*)d_in[7];
    const float* eps_w2     = (const float*)d_in[8];
    const float* eps_b2     = (const float*)d_in[9];
    const float* a_w1       = (const float*)d_in[10];
    const float* a_b1       = (const float*)d_in[11];
    const float* a_w2       = (const float*)d_in[12];
    const float* a_b2       = (const float*)d_in[13];

    const int D_IN = 128;
    const int N = in_sizes[0] / D_IN;
    const int E = in_sizes[2];
    const int L = in_sizes[6] / (H * H);

    float* out = (float*)d_out;

    __half *ghh, *nfh, *nfl, *hh0, *hl0, *Wh, *wnh, *gP;
    float *epsv, *ae;
    cudaGetSymbolAddress((void**)&ghh, g_ghh);
    cudaGetSymbolAddress((void**)&nfh, g_nfh);
    cudaGetSymbolAddress((void**)&nfl, g_nfl);
    cudaGetSymbolAddress((void**)&hh0, g_hh);
    cudaGetSymbolAddress((void**)&hl0, g_hl);
    cudaGetSymbolAddress((void**)&Wh,  g_Wh);
    cudaGetSymbolAddress((void**)&wnh, g_wnh);
    cudaGetSymbolAddress((void**)&gP,   g_P);
    cudaGetSymbolAddress((void**)&epsv, g_eps);
    cudaGetSymbolAddress((void**)&ae,   g_ae);

    constexpr int SMEM2 = NSTAGE * (16384 + 16384);   // proj (BK=32, 2-term) = 160KB
    constexpr int SMEM128 = 2 * 98304;                // 1-term BK=128 = 192KB
    cudaFuncSetAttribute(proj_gemm, cudaFuncAttributeMaxDynamicSharedMemorySize, SMEM2);
    cudaFuncSetAttribute(node_gemm, cudaFuncAttributeMaxDynamicSharedMemorySize, SMEM128);
    cudaFuncSetAttribute(edge_eps_gemm, cudaFuncAttributeMaxDynamicSharedMemorySize, SMEM128);

    // side stream + fork/join events (host-side resources, created once;
    // GPU work and captured graph identical on every call)
    static cudaStream_t s1 = nullptr;
    static cudaEvent_t evF = nullptr, evJ = nullptr;
    if (s1 == nullptr) {
        cudaStreamCreateWithFlags(&s1, cudaStreamNonBlocking);
        cudaEventCreateWithFlags(&evF, cudaEventDisableTiming);
        cudaEventCreateWithFlags(&evJ, cudaEventDisableTiming);
    }

    const int nblkN = (N + BM - 1) / BM;
    const int nblkE = (E + BM - 1) / BM;
    const size_t hbuf = (size_t)N_MAX * H;

    // main stream: weights + csr clear, then nf cvt + hist
    {
        int totw = L * 1024 * 256 + 128 * 256;
        prep_w<<<(totw + 255) / 256, 256>>>(a_w1, eps_w1, Wn_w, L, N);
        int n4 = (N * D_IN) / 4;
        int thr = (n4 > E) ? n4 : E;
        cvt_nf_hist<<<(thr + 255) / 256, 256>>>(node_feats, nfh, nfl, n4, dst, E);
    }

    // fork: CSR chain + gh conversion on side stream
    cudaEventRecord(evF, 0);
    cudaStreamWaitEvent(s1, evF, 0);
    csr_scan<<<1, 1024, 0, s1>>>(N, E);
    csr_scatter<<<(E + 255) / 256, 256, 0, s1>>>(src, dst, E);
    {
        int g4 = (E * H) / 4;
        cvt_gh_perm<<<(g4 + 255) / 256, 256, 0, s1>>>(gh, ghh, g4);
    }
    cudaEventRecord(evJ, s1);

    // main stream overlaps: input projection + layer-0 node GEMM
    proj_gemm<<<dim3(nblkN, 1, 1), NTH, SMEM2>>>(
        nfh, nfl, N, D_IN, wnh, Wn_b, out, hh0, hl0);

    for (int l = 0; l < L; l++) {
        const float* hcur = out + (size_t)l * N * H;
        float*       hnext = out + (size_t)(l + 1) * N * H;
        const __half* WhL = Wh + (size_t)l * 1024 * 256;
        __half* hhr = hh0 + (size_t)(l & 1) * hbuf;
        __half* hhw = hh0 + (size_t)((l + 1) & 1) * hbuf;
        __half* hlw = hl0 + (size_t)((l + 1) & 1) * hbuf;

        node_gemm<<<dim3(nblkN, 1, 2), NTH, SMEM128>>>(hhr, N, H, WhL, gP);

        if (l == 0) cudaStreamWaitEvent(0, evJ, 0);   // join: need ghh/srcp/dstp/off

        edge_eps_gemm<<<dim3(nblkE + nblkN, 1, 1), NTH, SMEM128>>>(
            ghh, E, hhr, N, nblkE, WhL,
            a_b1 + (size_t)l * H, a_w2 + (size_t)l * H, a_b2 + l, ae,
            gP, gP + hbuf,
            eps_b1 + (size_t)l * H, eps_w2 + (size_t)l * H, eps_b2 + l, epsv);

        msg_update<<<(N * 32 + 255) / 256, 256>>>(
            ae, ghh, hhr, hcur, epsv, hnext, hhw, hlw, N);
    }
}